// round 1
// baseline (speedup 1.0000x reference)
#include <cuda_runtime.h>
#include <math.h>

#define Bb 4
#define LQ 8400
#define Ee 256
#define HEADS 8
#define LEVELS 4
#define POINTS 4
#define HEAD_DIM 32
#define LVTOT 8500

// Scratch (no allocation allowed in kernel_launch)
__device__ float g_v[Bb * LVTOT * Ee];      // value @ Wv + bv          (34.8 MB)
__device__ float g_off[Bb * LQ * 256];      // query @ Woff + boff      (34.4 MB)
__device__ float g_aw[Bb * LQ * 128];       // query @ Wattn + battn    (17.2 MB)
__device__ float g_tmp[Bb * LQ * Ee];       // sampled pre-Wo output    (34.4 MB)

// ---------------------------------------------------------------------------
// Tiled fp32 GEMM: C[M,N] = A[M,K] @ W[K,N] + bias[N]
// BM=64, BN=64, BK=16, 256 threads, 4x4 per thread. N must be multiple of 64.
// ---------------------------------------------------------------------------
__global__ void gemm_bias_kernel(const float* __restrict__ A,
                                 const float* __restrict__ W,
                                 const float* __restrict__ bias,
                                 float* __restrict__ C,
                                 int M, int N, int K)
{
    const int BM = 64, BN = 64, BK = 16, TM = 4, TN = 4;
    __shared__ float As[BK][BM];
    __shared__ float Bs[BK][BN];

    int tid  = threadIdx.x;          // 0..255
    int brow = blockIdx.y * BM;
    int bcol = blockIdx.x * BN;
    int tx   = tid % 16;             // column group
    int ty   = tid / 16;             // row group

    float acc[TM][TN] = {};

    for (int k0 = 0; k0 < K; k0 += BK) {
        // Load A tile (BM x BK), transposed into smem
#pragma unroll
        for (int i = 0; i < 4; i++) {
            int idx = tid + i * 256;
            int r = idx / BK;
            int c = idx % BK;
            int gr = brow + r;
            As[c][r] = (gr < M) ? A[(size_t)gr * K + k0 + c] : 0.f;
        }
        // Load W tile (BK x BN)
#pragma unroll
        for (int i = 0; i < 4; i++) {
            int idx = tid + i * 256;
            int r = idx / BN;
            int c = idx % BN;
            Bs[r][c] = W[(size_t)(k0 + r) * N + bcol + c];
        }
        __syncthreads();

#pragma unroll
        for (int kk = 0; kk < BK; kk++) {
            float a[TM], b[TN];
#pragma unroll
            for (int i = 0; i < TM; i++) a[i] = As[kk][ty * TM + i];
#pragma unroll
            for (int j = 0; j < TN; j++) b[j] = Bs[kk][tx * TN + j];
#pragma unroll
            for (int i = 0; i < TM; i++)
#pragma unroll
                for (int j = 0; j < TN; j++)
                    acc[i][j] += a[i] * b[j];
        }
        __syncthreads();
    }

#pragma unroll
    for (int i = 0; i < TM; i++) {
        int r = brow + ty * TM + i;
        if (r >= M) continue;
#pragma unroll
        for (int j = 0; j < TN; j++) {
            int c = bcol + tx * TN + j;
            C[(size_t)r * N + c] = acc[i][j] + bias[c];
        }
    }
}

// ---------------------------------------------------------------------------
// Fused softmax + bilinear sampling. One warp per (b, q, h); lane = head dim.
// v layout [b, pos, h*32 + d] -> each corner gather is one coalesced 128B line.
// ---------------------------------------------------------------------------
__global__ void msda_sample_kernel(const float* __restrict__ ref,  // [B,LQ,LEVELS,2]
                                   float* __restrict__ out)        // g_tmp [B,LQ,E]
{
    int warp_global = blockIdx.x * (blockDim.x >> 5) + (threadIdx.x >> 5);
    int lane = threadIdx.x & 31;
    if (warp_global >= Bb * LQ * HEADS) return;

    int h  = warp_global % HEADS;
    int bq = warp_global / HEADS;          // b*LQ + q
    int b  = bq / LQ;

    // ---- softmax over 16 attention logits (lanes 0..15 hold one each) ----
    const float* awp = g_aw + (size_t)bq * 128 + h * 16;
    float logit = (lane < 16) ? awp[lane] : -1e30f;
    float m = logit;
#pragma unroll
    for (int o = 16; o > 0; o >>= 1) m = fmaxf(m, __shfl_xor_sync(0xffffffffu, m, o));
    float e = (lane < 16) ? __expf(logit - m) : 0.f;
    float s = e;
#pragma unroll
    for (int o = 16; o > 0; o >>= 1) s += __shfl_xor_sync(0xffffffffu, s, o);
    float w_lane = e / s;                  // weight for (l,p) = (lane/4, lane%4)

    // ---- offsets: 32 floats (l,p,xy), one per lane ----
    const float* offp = g_off + (size_t)bq * 256 + h * 32;
    float off_lane = offp[lane];

    const float* vbase = g_v + (size_t)b * LVTOT * Ee + h * HEAD_DIM + lane;

    const int lvlH[4]     = {80, 40, 20, 10};
    const int lvlW[4]     = {80, 40, 20, 10};
    const int lvlStart[4] = {0, 6400, 8000, 8400};

    float acc = 0.f;

#pragma unroll
    for (int l = 0; l < LEVELS; l++) {
        float rx = ref[((size_t)bq * LEVELS + l) * 2 + 0];
        float ry = ref[((size_t)bq * LEVELS + l) * 2 + 1];
        int Hl = lvlH[l], Wl = lvlW[l];
        const float* vlvl = vbase + (size_t)lvlStart[l] * Ee;

#pragma unroll
        for (int p = 0; p < POINTS; p++) {
            int pi   = l * POINTS + p;
            float ox = __shfl_sync(0xffffffffu, off_lane, pi * 2);
            float oy = __shfl_sync(0xffffffffu, off_lane, pi * 2 + 1);
            float aw = __shfl_sync(0xffffffffu, w_lane, pi);

            // x = loc_x * W - 0.5 where loc_x = ref_x + off_x / W
            float x = rx * (float)Wl + ox - 0.5f;
            float y = ry * (float)Hl + oy - 0.5f;
            float x0f = floorf(x), y0f = floorf(y);
            float wx = x - x0f, wy = y - y0f;
            int x0 = (int)x0f, y0 = (int)y0f;

            bool xin0 = (x0 >= 0) && (x0 < Wl);
            bool xin1 = (x0 + 1 >= 0) && (x0 + 1 < Wl);
            bool yin0 = (y0 >= 0) && (y0 < Hl);
            bool yin1 = (y0 + 1 >= 0) && (y0 + 1 < Hl);

            float v00 = 0.f, v01 = 0.f, v10 = 0.f, v11 = 0.f;
            if (yin0) {
                const float* row = vlvl + (size_t)(y0 * Wl) * Ee;
                if (xin0) v00 = row[(size_t)x0 * Ee];
                if (xin1) v01 = row[(size_t)(x0 + 1) * Ee];
            }
            if (yin1) {
                const float* row = vlvl + (size_t)((y0 + 1) * Wl) * Ee;
                if (xin0) v10 = row[(size_t)x0 * Ee];
                if (xin1) v11 = row[(size_t)(x0 + 1) * Ee];
            }
            float sample = v00 * (1.f - wx) * (1.f - wy) + v01 * wx * (1.f - wy)
                         + v10 * (1.f - wx) * wy         + v11 * wx * wy;
            acc = fmaf(aw, sample, acc);
        }
    }

    out[((size_t)bq * HEADS + h) * HEAD_DIM + lane] = acc;
}

// ---------------------------------------------------------------------------
extern "C" void kernel_launch(void* const* d_in, const int* in_sizes, int n_in,
                              void* d_out, int out_size)
{
    const float* query = (const float*)d_in[0];
    const float* ref   = (const float*)d_in[1];
    const float* value = (const float*)d_in[2];
    // d_in[3] = spatial_shapes (int32) — compile-time constants here
    const float* Wv    = (const float*)d_in[4];
    const float* bv    = (const float*)d_in[5];
    const float* Woff  = (const float*)d_in[6];
    const float* boff  = (const float*)d_in[7];
    const float* Wattn = (const float*)d_in[8];
    const float* battn = (const float*)d_in[9];
    const float* Wo    = (const float*)d_in[10];
    const float* bo    = (const float*)d_in[11];
    float* out = (float*)d_out;

    float *pv, *poff, *paw, *ptmp;
    cudaGetSymbolAddress((void**)&pv,   g_v);
    cudaGetSymbolAddress((void**)&poff, g_off);
    cudaGetSymbolAddress((void**)&paw,  g_aw);
    cudaGetSymbolAddress((void**)&ptmp, g_tmp);

    const int MV = Bb * LVTOT;   // 34000
    const int MQ = Bb * LQ;      // 33600

    // 1) v = value @ Wv + bv
    {
        dim3 grid(256 / 64, (MV + 63) / 64);
        gemm_bias_kernel<<<grid, 256>>>(value, Wv, bv, pv, MV, 256, 256);
    }
    // 2) off = query @ Woff + boff
    {
        dim3 grid(256 / 64, (MQ + 63) / 64);
        gemm_bias_kernel<<<grid, 256>>>(query, Woff, boff, poff, MQ, 256, 256);
    }
    // 3) aw logits = query @ Wattn + battn
    {
        dim3 grid(128 / 64, (MQ + 63) / 64);
        gemm_bias_kernel<<<grid, 256>>>(query, Wattn, battn, paw, MQ, 128, 256);
    }
    // 4) fused softmax + bilinear sampling -> g_tmp
    {
        int total_warps = Bb * LQ * HEADS;        // 268800
        int warps_per_block = 8;
        int blocks = (total_warps + warps_per_block - 1) / warps_per_block;
        msda_sample_kernel<<<blocks, warps_per_block * 32>>>(ref, ptmp);
    }
    // 5) out = g_tmp @ Wo + bo
    {
        dim3 grid(256 / 64, (MQ + 63) / 64);
        gemm_bias_kernel<<<grid, 256>>>(ptmp, Wo, bo, out, MQ, 256, 256);
    }
}

// round 2
// speedup vs baseline: 1.5226x; 1.5226x over previous
#include <cuda_runtime.h>
#include <math.h>

#define Bb 4
#define LQ 8400
#define Ee 256
#define HEADS 8
#define LEVELS 4
#define POINTS 4
#define HEAD_DIM 32
#define LVTOT 8500

// Scratch (no allocation allowed in kernel_launch)
__device__ float g_v[Bb * LVTOT * Ee];      // value @ Wv + bv
__device__ float g_off[Bb * LQ * 256];      // query @ Woff + boff
__device__ float g_aw[Bb * LQ * 128];       // query @ Wattn + battn
__device__ float g_tmp[Bb * LQ * Ee];       // sampled pre-Wo output

// ---------------------------------------------------------------------------
// fp32 GEMM: C[M,N] = A[M,K] @ W[K,N] + bias[N]
// BM=128, BN=128, BK=8, 256 threads, 8x8 per thread, double-buffered smem.
// Requires: N % 128 == 0, K % 8 == 0.
// ---------------------------------------------------------------------------
__global__ __launch_bounds__(256)
void sgemm128_bias(const float* __restrict__ A,
                   const float* __restrict__ W,
                   const float* __restrict__ bias,
                   float* __restrict__ C,
                   int M, int N, int K)
{
    const int BM = 128, BN = 128, BK = 8;
    __shared__ float As[2][BK][BM];
    __shared__ float Bs[2][BK][BN];

    int tid  = threadIdx.x;
    int brow = blockIdx.y * BM;
    int bcol = blockIdx.x * BN;

    // A tile load: thread -> one float4. row = tid/2 (0..127), col = (tid&1)*4
    int arow = tid >> 1;
    int acol = (tid & 1) * 4;
    // B tile load: row = tid/32 (0..7), col = (tid&31)*4
    int wrow = tid >> 5;
    int wcol = (tid & 31) * 4;

    bool avalid = (brow + arow) < M;
    const float* Aptr = A + (size_t)(brow + arow) * K + acol;
    const float* Wptr = W + (size_t)wrow * N + bcol + wcol;

    // thread tile position
    int ty = (tid / 16) * 8;
    int tx = (tid % 16) * 8;

    float acc[8][8];
#pragma unroll
    for (int i = 0; i < 8; i++)
#pragma unroll
        for (int j = 0; j < 8; j++) acc[i][j] = 0.f;

    // preload tile 0
    float4 a4 = avalid ? *(const float4*)Aptr : make_float4(0.f, 0.f, 0.f, 0.f);
    float4 b4 = *(const float4*)Wptr;
    As[0][acol + 0][arow] = a4.x;
    As[0][acol + 1][arow] = a4.y;
    As[0][acol + 2][arow] = a4.z;
    As[0][acol + 3][arow] = a4.w;
    *(float4*)&Bs[0][wrow][wcol] = b4;
    __syncthreads();

    int nk = K / BK;
    int buf = 0;
    for (int k0 = 0; k0 < nk; k0++) {
        bool has_next = (k0 + 1) < nk;
        float4 na, nb;
        if (has_next) {
            na = avalid ? *(const float4*)(Aptr + (k0 + 1) * BK)
                        : make_float4(0.f, 0.f, 0.f, 0.f);
            nb = *(const float4*)(Wptr + (size_t)(k0 + 1) * BK * N);
        }

#pragma unroll
        for (int kk = 0; kk < BK; kk++) {
            float4 a0 = *(const float4*)&As[buf][kk][ty];
            float4 a1 = *(const float4*)&As[buf][kk][ty + 4];
            float4 b0 = *(const float4*)&Bs[buf][kk][tx];
            float4 b1 = *(const float4*)&Bs[buf][kk][tx + 4];
            float ar[8] = {a0.x, a0.y, a0.z, a0.w, a1.x, a1.y, a1.z, a1.w};
            float br[8] = {b0.x, b0.y, b0.z, b0.w, b1.x, b1.y, b1.z, b1.w};
#pragma unroll
            for (int i = 0; i < 8; i++)
#pragma unroll
                for (int j = 0; j < 8; j++)
                    acc[i][j] = fmaf(ar[i], br[j], acc[i][j]);
        }

        if (has_next) {
            int nb_buf = buf ^ 1;
            As[nb_buf][acol + 0][arow] = na.x;
            As[nb_buf][acol + 1][arow] = na.y;
            As[nb_buf][acol + 2][arow] = na.z;
            As[nb_buf][acol + 3][arow] = na.w;
            *(float4*)&Bs[nb_buf][wrow][wcol] = nb;
            __syncthreads();
            buf = nb_buf;
        }
    }

    // epilogue: bias + store
    float bj[8];
#pragma unroll
    for (int j = 0; j < 8; j++) bj[j] = bias[bcol + tx + j];

#pragma unroll
    for (int i = 0; i < 8; i++) {
        int row = brow + ty + i;
        if (row >= M) continue;
        float* Crow = C + (size_t)row * N + bcol + tx;
        float4 o0, o1;
        o0.x = acc[i][0] + bj[0]; o0.y = acc[i][1] + bj[1];
        o0.z = acc[i][2] + bj[2]; o0.w = acc[i][3] + bj[3];
        o1.x = acc[i][4] + bj[4]; o1.y = acc[i][5] + bj[5];
        o1.z = acc[i][6] + bj[6]; o1.w = acc[i][7] + bj[7];
        *(float4*)&Crow[0] = o0;
        *(float4*)&Crow[4] = o1;
    }
}

// ---------------------------------------------------------------------------
// Fused softmax + bilinear sampling.
// One warp handles 4 heads of one (b,q): 8-lane group per head, lane = 4 dims.
// Each corner gather is one float4 per lane -> one 128B line per 8-lane group.
// ---------------------------------------------------------------------------
__global__ __launch_bounds__(256)
void msda_sample_kernel(const float* __restrict__ ref,  // [B,LQ,LEVELS,2]
                        float* __restrict__ out)        // g_tmp [B,LQ,E]
{
    int warp_global = blockIdx.x * (blockDim.x >> 5) + (threadIdx.x >> 5);
    if (warp_global >= Bb * LQ * 2) return;
    int lane = threadIdx.x & 31;
    int g = lane >> 3;       // head group within warp (0..3)
    int r = lane & 7;        // lane within group

    int hpair = warp_global & 1;   // low/high 4 heads
    int bq    = warp_global >> 1;  // b*LQ + q
    int b     = bq / LQ;
    int h     = hpair * 4 + g;

    // ---- softmax over 16 logits; lane r holds logits [2r, 2r+1] ----
    const float2* awp = (const float2*)(g_aw + (size_t)bq * 128 + h * 16);
    float2 lg = awp[r];
    float m = fmaxf(lg.x, lg.y);
#pragma unroll
    for (int o = 4; o > 0; o >>= 1) m = fmaxf(m, __shfl_xor_sync(0xffffffffu, m, o));
    float e0 = __expf(lg.x - m);
    float e1 = __expf(lg.y - m);
    float s = e0 + e1;
#pragma unroll
    for (int o = 4; o > 0; o >>= 1) s += __shfl_xor_sync(0xffffffffu, s, o);
    float inv = 1.f / s;
    float w0 = e0 * inv;   // weight for point 2r
    float w1 = e1 * inv;   // weight for point 2r+1

    // ---- offsets: lane r holds float4 = (x,y) of points 2r and 2r+1 ----
    const float4* offp = (const float4*)(g_off + (size_t)bq * 256 + h * 32);
    float4 off4 = offp[r];

    const float* vbase = g_v + (size_t)b * LVTOT * Ee + h * HEAD_DIM + r * 4;

    const int lvlHW[4]    = {80, 40, 20, 10};
    const int lvlStart[4] = {0, 6400, 8000, 8400};

    float4 acc = make_float4(0.f, 0.f, 0.f, 0.f);

#pragma unroll
    for (int l = 0; l < LEVELS; l++) {
        float rx = __ldg(&ref[((size_t)bq * LEVELS + l) * 2 + 0]);
        float ry = __ldg(&ref[((size_t)bq * LEVELS + l) * 2 + 1]);
        int HW = lvlHW[l];
        const float* vlvl = vbase + (size_t)lvlStart[l] * Ee;

#pragma unroll
        for (int p = 0; p < POINTS; p++) {
            int pi  = l * POINTS + p;
            int src = (g << 3) + (pi >> 1);
            float ox, oy, aw;
            if (pi & 1) {
                ox = __shfl_sync(0xffffffffu, off4.z, src);
                oy = __shfl_sync(0xffffffffu, off4.w, src);
                aw = __shfl_sync(0xffffffffu, w1,     src);
            } else {
                ox = __shfl_sync(0xffffffffu, off4.x, src);
                oy = __shfl_sync(0xffffffffu, off4.y, src);
                aw = __shfl_sync(0xffffffffu, w0,     src);
            }

            float x = fmaf(rx, (float)HW, ox - 0.5f);
            float y = fmaf(ry, (float)HW, oy - 0.5f);
            float x0f = floorf(x), y0f = floorf(y);
            float wx = x - x0f, wy = y - y0f;
            int x0 = (int)x0f, y0 = (int)y0f;
            int x1 = x0 + 1,   y1 = y0 + 1;

            float vx0 = (x0 >= 0 && x0 < HW) ? 1.f : 0.f;
            float vx1 = (x1 >= 0 && x1 < HW) ? 1.f : 0.f;
            float vy0 = (y0 >= 0 && y0 < HW) ? 1.f : 0.f;
            float vy1 = (y1 >= 0 && y1 < HW) ? 1.f : 0.f;

            int cx0 = min(max(x0, 0), HW - 1);
            int cx1 = min(max(x1, 0), HW - 1);
            int cy0 = min(max(y0, 0), HW - 1);
            int cy1 = min(max(y1, 0), HW - 1);

            float wx1 = 1.f - wx, wy1 = 1.f - wy;
            float c00 = aw * wx1 * wy1 * vx0 * vy0;
            float c01 = aw * wx  * wy1 * vx1 * vy0;
            float c10 = aw * wx1 * wy  * vx0 * vy1;
            float c11 = aw * wx  * wy  * vx1 * vy1;

            const float4* p00 = (const float4*)(vlvl + (size_t)(cy0 * HW + cx0) * Ee);
            const float4* p01 = (const float4*)(vlvl + (size_t)(cy0 * HW + cx1) * Ee);
            const float4* p10 = (const float4*)(vlvl + (size_t)(cy1 * HW + cx0) * Ee);
            const float4* p11 = (const float4*)(vlvl + (size_t)(cy1 * HW + cx1) * Ee);

            float4 v00 = __ldg(p00);
            float4 v01 = __ldg(p01);
            float4 v10 = __ldg(p10);
            float4 v11 = __ldg(p11);

            acc.x = fmaf(c00, v00.x, fmaf(c01, v01.x, fmaf(c10, v10.x, fmaf(c11, v11.x, acc.x))));
            acc.y = fmaf(c00, v00.y, fmaf(c01, v01.y, fmaf(c10, v10.y, fmaf(c11, v11.y, acc.y))));
            acc.z = fmaf(c00, v00.z, fmaf(c01, v01.z, fmaf(c10, v10.z, fmaf(c11, v11.z, acc.z))));
            acc.w = fmaf(c00, v00.w, fmaf(c01, v01.w, fmaf(c10, v10.w, fmaf(c11, v11.w, acc.w))));
        }
    }

    *(float4*)(out + (size_t)bq * Ee + h * HEAD_DIM + r * 4) = acc;
}

// ---------------------------------------------------------------------------
extern "C" void kernel_launch(void* const* d_in, const int* in_sizes, int n_in,
                              void* d_out, int out_size)
{
    const float* query = (const float*)d_in[0];
    const float* ref   = (const float*)d_in[1];
    const float* value = (const float*)d_in[2];
    const float* Wv    = (const float*)d_in[4];
    const float* bv    = (const float*)d_in[5];
    const float* Woff  = (const float*)d_in[6];
    const float* boff  = (const float*)d_in[7];
    const float* Wattn = (const float*)d_in[8];
    const float* battn = (const float*)d_in[9];
    const float* Wo    = (const float*)d_in[10];
    const float* bo    = (const float*)d_in[11];
    float* out = (float*)d_out;

    float *pv, *poff, *paw, *ptmp;
    cudaGetSymbolAddress((void**)&pv,   g_v);
    cudaGetSymbolAddress((void**)&poff, g_off);
    cudaGetSymbolAddress((void**)&paw,  g_aw);
    cudaGetSymbolAddress((void**)&ptmp, g_tmp);

    const int MV = Bb * LVTOT;   // 34000
    const int MQ = Bb * LQ;      // 33600

    // 1) v = value @ Wv + bv
    {
        dim3 grid(256 / 128, (MV + 127) / 128);
        sgemm128_bias<<<grid, 256>>>(value, Wv, bv, pv, MV, 256, 256);
    }
    // 2) off = query @ Woff + boff
    {
        dim3 grid(256 / 128, (MQ + 127) / 128);
        sgemm128_bias<<<grid, 256>>>(query, Woff, boff, poff, MQ, 256, 256);
    }
    // 3) aw logits = query @ Wattn + battn
    {
        dim3 grid(128 / 128, (MQ + 127) / 128);
        sgemm128_bias<<<grid, 256>>>(query, Wattn, battn, paw, MQ, 128, 256);
    }
    // 4) fused softmax + bilinear sampling -> g_tmp
    {
        int total_warps = Bb * LQ * 2;   // 67200 warps (4 heads each)
        int warps_per_block = 8;
        int blocks = (total_warps + warps_per_block - 1) / warps_per_block;
        msda_sample_kernel<<<blocks, warps_per_block * 32>>>(ref, ptmp);
    }
    // 5) out = g_tmp @ Wo + bo
    {
        dim3 grid(256 / 128, (MQ + 127) / 128);
        sgemm128_bias<<<grid, 256>>>(ptmp, Wo, bo, out, MQ, 256, 256);
    }
}

// round 5
// speedup vs baseline: 2.8062x; 1.8431x over previous
#include <cuda_runtime.h>
#include <cuda_bf16.h>
#include <math.h>
#include <stdint.h>

#define Bb 4
#define LQ 8400
#define Ee 256
#define HEADS 8
#define LEVELS 4
#define POINTS 4
#define HEAD_DIM 32
#define LVTOT 8500
#define KDIM 256

#define MQ (Bb * LQ)     // 33600
#define MV (Bb * LVTOT)  // 34000

// ---------------- scratch (device globals; no allocation allowed) ----------
__device__ float g_v[MV * Ee];        // value @ Wv + bv (f32, for sampler)
__device__ float g_off[MQ * 256];
__device__ float g_aw[MQ * 128];

__device__ __nv_bfloat16 g_qhi[MQ * KDIM];
__device__ __nv_bfloat16 g_qlo[MQ * KDIM];
__device__ __nv_bfloat16 g_vhi[MV * KDIM];
__device__ __nv_bfloat16 g_vlo[MV * KDIM];
__device__ __nv_bfloat16 g_thi[MQ * KDIM];   // sampler output, bf16 hi
__device__ __nv_bfloat16 g_tlo[MQ * KDIM];   // sampler output, bf16 lo
// transposed weights [N][K] bf16 hi/lo
// sizes: Wv^T 256*256=65536, Woff^T 256*256=65536, Wattn^T 128*256=32768, Wo^T 256*256=65536
#define WT_WV    0
#define WT_WOFF  65536
#define WT_WATTN 131072
#define WT_WO    163840
#define WT_TOTAL 229376          // 163840 + 65536  (was 196608: OVERFLOW bug in R3/R4)
__device__ __nv_bfloat16 g_wt_hi[WT_TOTAL];
__device__ __nv_bfloat16 g_wt_lo[WT_TOTAL];

// ---------------- helpers ----------------------------------------------
#define SMEM_SWIZZLE_128B(byte_offset) \
    ((byte_offset) ^ (((byte_offset) >> 3) & 0x70))

__device__ __forceinline__ uint32_t smem_u32(const void* p) {
    uint32_t a;
    asm("{ .reg .u64 t; cvta.to.shared.u64 t, %1; cvt.u32.u64 %0, t; }"
        : "=r"(a) : "l"(p));
    return a;
}

__device__ __forceinline__ void cp16(uint32_t dst, const void* src, bool v) {
    asm volatile("cp.async.cg.shared.global [%0], [%1], 16, %2;"
                 :: "r"(dst), "l"(src), "r"(v ? 16u : 0u));
}

__device__ __forceinline__ void cp_commit_wait() {
    asm volatile("cp.async.commit_group;" ::: "memory");
    asm volatile("cp.async.wait_group 0;" ::: "memory");
}

__device__ __forceinline__ void ldm_x4(uint32_t* r, uint32_t addr) {
    asm volatile("ldmatrix.sync.aligned.m8n8.x4.shared.b16 {%0,%1,%2,%3}, [%4];"
                 : "=r"(r[0]), "=r"(r[1]), "=r"(r[2]), "=r"(r[3]) : "r"(addr));
}

__device__ __forceinline__ void mma16816(float* c, const uint32_t* a, const uint32_t* b) {
    asm volatile("mma.sync.aligned.m16n8k16.row.col.f32.bf16.bf16.f32 "
                 "{%0,%1,%2,%3}, {%4,%5,%6,%7}, {%8,%9}, {%0,%1,%2,%3};"
                 : "+f"(c[0]), "+f"(c[1]), "+f"(c[2]), "+f"(c[3])
                 : "r"(a[0]), "r"(a[1]), "r"(a[2]), "r"(a[3]),
                   "r"(b[0]), "r"(b[1]));
}

// ---------------------------------------------------------------------------
// split fp32 -> bf16 hi/lo
// ---------------------------------------------------------------------------
__global__ void split_bf16_kernel(const float4* __restrict__ x,
                                  uint2* __restrict__ hi, uint2* __restrict__ lo,
                                  int n4)
{
    int i = blockIdx.x * blockDim.x + threadIdx.x;
    if (i >= n4) return;
    float4 v = x[i];
    __nv_bfloat16 h0 = __float2bfloat16_rn(v.x);
    __nv_bfloat16 h1 = __float2bfloat16_rn(v.y);
    __nv_bfloat16 h2 = __float2bfloat16_rn(v.z);
    __nv_bfloat16 h3 = __float2bfloat16_rn(v.w);
    __nv_bfloat16 l0 = __float2bfloat16_rn(v.x - __bfloat162float(h0));
    __nv_bfloat16 l1 = __float2bfloat16_rn(v.y - __bfloat162float(h1));
    __nv_bfloat16 l2 = __float2bfloat16_rn(v.z - __bfloat162float(h2));
    __nv_bfloat16 l3 = __float2bfloat16_rn(v.w - __bfloat162float(h3));
    __nv_bfloat162 hp0; hp0.x = h0; hp0.y = h1;
    __nv_bfloat162 hp1; hp1.x = h2; hp1.y = h3;
    __nv_bfloat162 lp0; lp0.x = l0; lp0.y = l1;
    __nv_bfloat162 lp1; lp1.x = l2; lp1.y = l3;
    uint2 ho, loo;
    ho.x  = *(uint32_t*)&hp0; ho.y  = *(uint32_t*)&hp1;
    loo.x = *(uint32_t*)&lp0; loo.y = *(uint32_t*)&lp1;
    hi[i] = ho;
    lo[i] = loo;
}

// transpose W[K][N] -> Wt[N][K] with bf16 hi/lo split
__global__ void tsplit_kernel(const float* __restrict__ W,
                              __nv_bfloat16* __restrict__ thi,
                              __nv_bfloat16* __restrict__ tlo,
                              int Kd, int Nd)
{
    int idx = blockIdx.x * blockDim.x + threadIdx.x;
    if (idx >= Kd * Nd) return;
    int k = idx / Nd, n = idx % Nd;
    float v = W[idx];
    __nv_bfloat16 h = __float2bfloat16_rn(v);
    thi[(size_t)n * Kd + k] = h;
    tlo[(size_t)n * Kd + k] = __float2bfloat16_rn(v - __bfloat162float(h));
}

// ---------------------------------------------------------------------------
// mma.sync bf16x3 GEMM: C[M,N] = (Ahi+Alo)[M,K] @ (Bhi+Blo)^T + bias
// CTA: 128x128, 8 warps of 64x32. K = 256 staged in 4 chunks of 64.
// ---------------------------------------------------------------------------
__global__ __launch_bounds__(256, 1)
void gemm_mma_bf16x3(const __nv_bfloat16* __restrict__ Ahi,
                     const __nv_bfloat16* __restrict__ Alo,
                     const __nv_bfloat16* __restrict__ Bhi,   // [N][K]
                     const __nv_bfloat16* __restrict__ Blo,   // [N][K]
                     const float* __restrict__ bias,
                     float* __restrict__ C,
                     int M, int N)
{
    extern __shared__ char smem[];
    const uint32_t sa_hi = smem_u32(smem);
    const uint32_t sa_lo = sa_hi + 16384u;
    const uint32_t sb_hi = sa_hi + 32768u;
    const uint32_t sb_lo = sa_hi + 49152u;

    const int tid = threadIdx.x, lane = tid & 31, wid = tid >> 5;
    const int brow = blockIdx.y * 128, bcol = blockIdx.x * 128;
    const int wr = (wid >> 2) * 64;   // warp row base within tile
    const int wc = (wid & 3) * 32;    // warp col base within tile

    float acc[4][4][4];
#pragma unroll
    for (int i = 0; i < 4; i++)
#pragma unroll
        for (int j = 0; j < 4; j++)
#pragma unroll
            for (int k = 0; k < 4; k++) acc[i][j][k] = 0.f;

    // ldmatrix per-lane address components
    const int a_r  = wr + (lane & 15);
    const int a_kx = (lane >> 4) << 4;                        // 0 / 16 bytes
    const int b_r0 = wc + (lane & 7) + ((lane >> 4) << 3);
    const int b_kx = ((lane >> 3) & 1) << 4;

    for (int kc = 0; kc < KDIM / 64; kc++) {
        // ---- stage A/B hi+lo (each 128 rows x 128 bytes, swizzled) ----
        for (int t = tid; t < 1024; t += 256) {
            int r = t >> 3, j = t & 7;
            uint32_t d = SMEM_SWIZZLE_128B((uint32_t)(r * 128 + j * 16));
            size_t asrc = (size_t)(brow + r) * KDIM + kc * 64 + j * 8;
            size_t bsrc = (size_t)(bcol + r) * KDIM + kc * 64 + j * 8;
            bool av = (brow + r) < M;
            cp16(sa_hi + d, Ahi + asrc, av);
            cp16(sa_lo + d, Alo + asrc, av);
            cp16(sb_hi + d, Bhi + bsrc, true);
            cp16(sb_lo + d, Blo + bsrc, true);
        }
        cp_commit_wait();
        __syncthreads();

#pragma unroll
        for (int kk = 0; kk < 4; kk++) {
            const uint32_t kbA = (uint32_t)(kk * 32 + a_kx);
            const uint32_t kbB = (uint32_t)(kk * 32 + b_kx);

            uint32_t ahi[4][4], bhi[4][2];
#pragma unroll
            for (int mi = 0; mi < 4; mi++)
                ldm_x4(ahi[mi], sa_hi + SMEM_SWIZZLE_128B((uint32_t)((a_r + mi * 16) * 128) + kbA));
#pragma unroll
            for (int nj = 0; nj < 2; nj++) {
                uint32_t rr[4];
                ldm_x4(rr, sb_hi + SMEM_SWIZZLE_128B((uint32_t)((b_r0 + nj * 16) * 128) + kbB));
                bhi[nj * 2][0] = rr[0]; bhi[nj * 2][1] = rr[1];
                bhi[nj * 2 + 1][0] = rr[2]; bhi[nj * 2 + 1][1] = rr[3];
            }
            // pass 0: hi * hi
#pragma unroll
            for (int mi = 0; mi < 4; mi++)
#pragma unroll
                for (int ni = 0; ni < 4; ni++)
                    mma16816(acc[mi][ni], ahi[mi], bhi[ni]);

            uint32_t blo[4][2];
#pragma unroll
            for (int nj = 0; nj < 2; nj++) {
                uint32_t rr[4];
                ldm_x4(rr, sb_lo + SMEM_SWIZZLE_128B((uint32_t)((b_r0 + nj * 16) * 128) + kbB));
                blo[nj * 2][0] = rr[0]; blo[nj * 2][1] = rr[1];
                blo[nj * 2 + 1][0] = rr[2]; blo[nj * 2 + 1][1] = rr[3];
            }
            // pass 1: hi * lo
#pragma unroll
            for (int mi = 0; mi < 4; mi++)
#pragma unroll
                for (int ni = 0; ni < 4; ni++)
                    mma16816(acc[mi][ni], ahi[mi], blo[ni]);

            uint32_t alo[4][4];
#pragma unroll
            for (int mi = 0; mi < 4; mi++)
                ldm_x4(alo[mi], sa_lo + SMEM_SWIZZLE_128B((uint32_t)((a_r + mi * 16) * 128) + kbA));
            // pass 2: lo * hi
#pragma unroll
            for (int mi = 0; mi < 4; mi++)
#pragma unroll
                for (int ni = 0; ni < 4; ni++)
                    mma16816(acc[mi][ni], alo[mi], bhi[ni]);
        }
        __syncthreads();
    }

    // ---- epilogue: bias + float2 stores ----
    const int row0 = brow + wr + (lane >> 2);
#pragma unroll
    for (int ni = 0; ni < 4; ni++) {
        int col = bcol + wc + ni * 8 + (lane & 3) * 2;
        float2 bb = *(const float2*)&bias[col];
#pragma unroll
        for (int mi = 0; mi < 4; mi++) {
            int r0 = row0 + mi * 16;
            if (r0 < M) {
                float2 o;
                o.x = acc[mi][ni][0] + bb.x;
                o.y = acc[mi][ni][1] + bb.y;
                *(float2*)(C + (size_t)r0 * N + col) = o;
            }
            int r1 = r0 + 8;
            if (r1 < M) {
                float2 o;
                o.x = acc[mi][ni][2] + bb.x;
                o.y = acc[mi][ni][3] + bb.y;
                *(float2*)(C + (size_t)r1 * N + col) = o;
            }
        }
    }
}

// ---------------------------------------------------------------------------
// Fused softmax + bilinear sampling; emits bf16 hi/lo directly for final GEMM.
// ---------------------------------------------------------------------------
__global__ __launch_bounds__(256)
void msda_sample_kernel(const float* __restrict__ ref)
{
    int warp_global = blockIdx.x * (blockDim.x >> 5) + (threadIdx.x >> 5);
    if (warp_global >= Bb * LQ * 2) return;
    int lane = threadIdx.x & 31;
    int g = lane >> 3;
    int r = lane & 7;

    int hpair = warp_global & 1;
    int bq    = warp_global >> 1;
    int b     = bq / LQ;
    int hh    = hpair * 4 + g;

    const float2* awp = (const float2*)(g_aw + (size_t)bq * 128 + hh * 16);
    float2 lg = awp[r];
    float m = fmaxf(lg.x, lg.y);
#pragma unroll
    for (int o = 4; o > 0; o >>= 1) m = fmaxf(m, __shfl_xor_sync(0xffffffffu, m, o));
    float e0 = __expf(lg.x - m);
    float e1 = __expf(lg.y - m);
    float s = e0 + e1;
#pragma unroll
    for (int o = 4; o > 0; o >>= 1) s += __shfl_xor_sync(0xffffffffu, s, o);
    float inv = 1.f / s;
    float w0 = e0 * inv;
    float w1 = e1 * inv;

    const float4* offp = (const float4*)(g_off + (size_t)bq * 256 + hh * 32);
    float4 off4 = offp[r];

    const float* vbase = g_v + (size_t)b * LVTOT * Ee + hh * HEAD_DIM + r * 4;

    const int lvlHW[4]    = {80, 40, 20, 10};
    const int lvlStart[4] = {0, 6400, 8000, 8400};

    float4 acc = make_float4(0.f, 0.f, 0.f, 0.f);

#pragma unroll
    for (int l = 0; l < LEVELS; l++) {
        float rx = __ldg(&ref[((size_t)bq * LEVELS + l) * 2 + 0]);
        float ry = __ldg(&ref[((size_t)bq * LEVELS + l) * 2 + 1]);
        int HW = lvlHW[l];
        const float* vlvl = vbase + (size_t)lvlStart[l] * Ee;

#pragma unroll
        for (int p = 0; p < POINTS; p++) {
            int pi  = l * POINTS + p;
            int src = (g << 3) + (pi >> 1);
            float ox, oy, aw;
            if (pi & 1) {
                ox = __shfl_sync(0xffffffffu, off4.z, src);
                oy = __shfl_sync(0xffffffffu, off4.w, src);
                aw = __shfl_sync(0xffffffffu, w1,     src);
            } else {
                ox = __shfl_sync(0xffffffffu, off4.x, src);
                oy = __shfl_sync(0xffffffffu, off4.y, src);
                aw = __shfl_sync(0xffffffffu, w0,     src);
            }

            float x = fmaf(rx, (float)HW, ox - 0.5f);
            float y = fmaf(ry, (float)HW, oy - 0.5f);
            float x0f = floorf(x), y0f = floorf(y);
            float wx = x - x0f, wy = y - y0f;
            int x0 = (int)x0f, y0 = (int)y0f;
            int x1 = x0 + 1,   y1 = y0 + 1;

            float vx0 = (x0 >= 0 && x0 < HW) ? 1.f : 0.f;
            float vx1 = (x1 >= 0 && x1 < HW) ? 1.f : 0.f;
            float vy0 = (y0 >= 0 && y0 < HW) ? 1.f : 0.f;
            float vy1 = (y1 >= 0 && y1 < HW) ? 1.f : 0.f;

            int cx0 = min(max(x0, 0), HW - 1);
            int cx1 = min(max(x1, 0), HW - 1);
            int cy0 = min(max(y0, 0), HW - 1);
            int cy1 = min(max(y1, 0), HW - 1);

            float wx1 = 1.f - wx, wy1 = 1.f - wy;
            float c00 = aw * wx1 * wy1 * vx0 * vy0;
            float c01 = aw * wx  * wy1 * vx1 * vy0;
            float c10 = aw * wx1 * wy  * vx0 * vy1;
            float c11 = aw * wx  * wy  * vx1 * vy1;

            float4 v00 = __ldg((const float4*)(vlvl + (size_t)(cy0 * HW + cx0) * Ee));
            float4 v01 = __ldg((const float4*)(vlvl + (size_t)(cy0 * HW + cx1) * Ee));
            float4 v10 = __ldg((const float4*)(vlvl + (size_t)(cy1 * HW + cx0) * Ee));
            float4 v11 = __ldg((const float4*)(vlvl + (size_t)(cy1 * HW + cx1) * Ee));

            acc.x = fmaf(c00, v00.x, fmaf(c01, v01.x, fmaf(c10, v10.x, fmaf(c11, v11.x, acc.x))));
            acc.y = fmaf(c00, v00.y, fmaf(c01, v01.y, fmaf(c10, v10.y, fmaf(c11, v11.y, acc.y))));
            acc.z = fmaf(c00, v00.z, fmaf(c01, v01.z, fmaf(c10, v10.z, fmaf(c11, v11.z, acc.z))));
            acc.w = fmaf(c00, v00.w, fmaf(c01, v01.w, fmaf(c10, v10.w, fmaf(c11, v11.w, acc.w))));
        }
    }

    // write bf16 hi/lo directly (feeds final GEMM)
    __nv_bfloat16 bh0 = __float2bfloat16_rn(acc.x);
    __nv_bfloat16 bh1 = __float2bfloat16_rn(acc.y);
    __nv_bfloat16 bh2 = __float2bfloat16_rn(acc.z);
    __nv_bfloat16 bh3 = __float2bfloat16_rn(acc.w);
    __nv_bfloat16 bl0 = __float2bfloat16_rn(acc.x - __bfloat162float(bh0));
    __nv_bfloat16 bl1 = __float2bfloat16_rn(acc.y - __bfloat162float(bh1));
    __nv_bfloat16 bl2 = __float2bfloat16_rn(acc.z - __bfloat162float(bh2));
    __nv_bfloat16 bl3 = __float2bfloat16_rn(acc.w - __bfloat162float(bh3));
    __nv_bfloat162 hp0; hp0.x = bh0; hp0.y = bh1;
    __nv_bfloat162 hp1; hp1.x = bh2; hp1.y = bh3;
    __nv_bfloat162 lp0; lp0.x = bl0; lp0.y = bl1;
    __nv_bfloat162 lp1; lp1.x = bl2; lp1.y = bl3;
    size_t o4 = (size_t)bq * 256 + hh * 32 + r * 4;
    uint2 ho; ho.x = *(uint32_t*)&hp0; ho.y = *(uint32_t*)&hp1;
    uint2 lo; lo.x = *(uint32_t*)&lp0; lo.y = *(uint32_t*)&lp1;
    *(uint2*)(g_thi + o4) = ho;
    *(uint2*)(g_tlo + o4) = lo;
}

// ---------------------------------------------------------------------------
extern "C" void kernel_launch(void* const* d_in, const int* in_sizes, int n_in,
                              void* d_out, int out_size)
{
    const float* query = (const float*)d_in[0];
    const float* ref   = (const float*)d_in[1];
    const float* value = (const float*)d_in[2];
    const float* Wv    = (const float*)d_in[4];
    const float* bv    = (const float*)d_in[5];
    const float* Woff  = (const float*)d_in[6];
    const float* boff  = (const float*)d_in[7];
    const float* Wattn = (const float*)d_in[8];
    const float* battn = (const float*)d_in[9];
    const float* Wo    = (const float*)d_in[10];
    const float* bo    = (const float*)d_in[11];
    float* out = (float*)d_out;

    float *pv, *poff, *paw;
    __nv_bfloat16 *pqhi, *pqlo, *pvhi, *pvlo, *pthi, *ptlo, *pwhi, *pwlo;
    cudaGetSymbolAddress((void**)&pv,   g_v);
    cudaGetSymbolAddress((void**)&poff, g_off);
    cudaGetSymbolAddress((void**)&paw,  g_aw);
    cudaGetSymbolAddress((void**)&pqhi, g_qhi);
    cudaGetSymbolAddress((void**)&pqlo, g_qlo);
    cudaGetSymbolAddress((void**)&pvhi, g_vhi);
    cudaGetSymbolAddress((void**)&pvlo, g_vlo);
    cudaGetSymbolAddress((void**)&pthi, g_thi);
    cudaGetSymbolAddress((void**)&ptlo, g_tlo);
    cudaGetSymbolAddress((void**)&pwhi, g_wt_hi);
    cudaGetSymbolAddress((void**)&pwlo, g_wt_lo);

    cudaFuncSetAttribute(gemm_mma_bf16x3,
                         cudaFuncAttributeMaxDynamicSharedMemorySize, 65536);

    // ---- operand conversions ----
    {
        int n4 = MV * KDIM / 4;
        split_bf16_kernel<<<(n4 + 255) / 256, 256>>>((const float4*)value,
                                                     (uint2*)pvhi, (uint2*)pvlo, n4);
    }
    {
        int n4 = MQ * KDIM / 4;
        split_bf16_kernel<<<(n4 + 255) / 256, 256>>>((const float4*)query,
                                                     (uint2*)pqhi, (uint2*)pqlo, n4);
    }
    tsplit_kernel<<<(256 * 256 + 255) / 256, 256>>>(Wv,    pwhi + WT_WV,    pwlo + WT_WV,    256, 256);
    tsplit_kernel<<<(256 * 256 + 255) / 256, 256>>>(Woff,  pwhi + WT_WOFF,  pwlo + WT_WOFF,  256, 256);
    tsplit_kernel<<<(256 * 128 + 255) / 256, 256>>>(Wattn, pwhi + WT_WATTN, pwlo + WT_WATTN, 256, 128);
    tsplit_kernel<<<(256 * 256 + 255) / 256, 256>>>(Wo,    pwhi + WT_WO,    pwlo + WT_WO,    256, 256);

    // ---- GEMMs on tensor cores (mma.sync) ----
    {
        dim3 grid(2, (MV + 127) / 128);
        gemm_mma_bf16x3<<<grid, 256, 65536>>>(pvhi, pvlo,
            pwhi + WT_WV, pwlo + WT_WV, bv, pv, MV, 256);
    }
    {
        dim3 grid(2, (MQ + 127) / 128);
        gemm_mma_bf16x3<<<grid, 256, 65536>>>(pqhi, pqlo,
            pwhi + WT_WOFF, pwlo + WT_WOFF, boff, poff, MQ, 256);
    }
    {
        dim3 grid(1, (MQ + 127) / 128);
        gemm_mma_bf16x3<<<grid, 256, 65536>>>(pqhi, pqlo,
            pwhi + WT_WATTN, pwlo + WT_WATTN, battn, paw, MQ, 128);
    }

    // ---- fused softmax + sampling (emits bf16 hi/lo) ----
    {
        int total_warps = Bb * LQ * 2;
        int blocks = (total_warps + 7) / 8;
        msda_sample_kernel<<<blocks, 256>>>(ref);
    }

    // ---- final GEMM: out = sampled @ Wo + bo ----
    {
        dim3 grid(2, (MQ + 127) / 128);
        gemm_mma_bf16x3<<<grid, 256, 65536>>>(pthi, ptlo,
            pwhi + WT_WO, pwlo + WT_WO, bo, out, MQ, 256);
    }
}

// round 6
// speedup vs baseline: 3.2359x; 1.1531x over previous
#include <cuda_runtime.h>
#include <cuda_bf16.h>
#include <math.h>
#include <stdint.h>

#define Bb 4
#define LQ 8400
#define Ee 256
#define HEADS 8
#define LEVELS 4
#define POINTS 4
#define HEAD_DIM 32
#define LVTOT 8500
#define KDIM 256

#define MQ (Bb * LQ)     // 33600
#define MV (Bb * LVTOT)  // 34000

// ---------------- scratch (device globals; no allocation allowed) ----------
__device__ float g_v[MV * Ee];            // value @ Wv + bv (f32, sampler input)
__device__ float g_offaw[MQ * 384];       // [off(256) | aw(128)] fused GEMM output
__device__ float g_tmp[MQ * Ee];          // sampler output (f32)
__device__ float g_bias_comb[384];

// transposed weights [N][K] bf16 hi/lo
// Wv^T 65536 | comb(Woff^T 256 rows + Wattn^T 128 rows) 98304 | Wo^T 65536
#define WT_WV    0
#define WT_COMB  65536
#define WT_WO    163840
#define WT_TOTAL 229376
__device__ __nv_bfloat16 g_wt_hi[WT_TOTAL];
__device__ __nv_bfloat16 g_wt_lo[WT_TOTAL];

// ---------------- helpers ----------------------------------------------
#define SMEM_SWIZZLE_128B(byte_offset) \
    ((byte_offset) ^ (((byte_offset) >> 3) & 0x70))

__device__ __forceinline__ uint32_t smem_u32(const void* p) {
    uint32_t a;
    asm("{ .reg .u64 t; cvta.to.shared.u64 t, %1; cvt.u32.u64 %0, t; }"
        : "=r"(a) : "l"(p));
    return a;
}

__device__ __forceinline__ void cp16(uint32_t dst, const void* src) {
    asm volatile("cp.async.cg.shared.global [%0], [%1], 16;"
                 :: "r"(dst), "l"(src));
}

__device__ __forceinline__ void cp_commit() {
    asm volatile("cp.async.commit_group;" ::: "memory");
}
__device__ __forceinline__ void cp_wait0() {
    asm volatile("cp.async.wait_group 0;" ::: "memory");
}

__device__ __forceinline__ void ldm_x4(uint32_t* r, uint32_t addr) {
    asm volatile("ldmatrix.sync.aligned.m8n8.x4.shared.b16 {%0,%1,%2,%3}, [%4];"
                 : "=r"(r[0]), "=r"(r[1]), "=r"(r[2]), "=r"(r[3]) : "r"(addr));
}

__device__ __forceinline__ void mma16816(float* c, const uint32_t* a, const uint32_t* b) {
    asm volatile("mma.sync.aligned.m16n8k16.row.col.f32.bf16.bf16.f32 "
                 "{%0,%1,%2,%3}, {%4,%5,%6,%7}, {%8,%9}, {%0,%1,%2,%3};"
                 : "+f"(c[0]), "+f"(c[1]), "+f"(c[2]), "+f"(c[3])
                 : "r"(a[0]), "r"(a[1]), "r"(a[2]), "r"(a[3]),
                   "r"(b[0]), "r"(b[1]));
}

// pack float4 -> bf16 hi (uint2) and lo (uint2)
__device__ __forceinline__ void split4(float4 v, uint2& ho, uint2& lo) {
    __nv_bfloat16 h0 = __float2bfloat16_rn(v.x);
    __nv_bfloat16 h1 = __float2bfloat16_rn(v.y);
    __nv_bfloat16 h2 = __float2bfloat16_rn(v.z);
    __nv_bfloat16 h3 = __float2bfloat16_rn(v.w);
    __nv_bfloat16 l0 = __float2bfloat16_rn(v.x - __bfloat162float(h0));
    __nv_bfloat16 l1 = __float2bfloat16_rn(v.y - __bfloat162float(h1));
    __nv_bfloat16 l2 = __float2bfloat16_rn(v.z - __bfloat162float(h2));
    __nv_bfloat16 l3 = __float2bfloat16_rn(v.w - __bfloat162float(h3));
    __nv_bfloat162 hp0; hp0.x = h0; hp0.y = h1;
    __nv_bfloat162 hp1; hp1.x = h2; hp1.y = h3;
    __nv_bfloat162 lp0; lp0.x = l0; lp0.y = l1;
    __nv_bfloat162 lp1; lp1.x = l2; lp1.y = l3;
    ho.x = *(uint32_t*)&hp0; ho.y = *(uint32_t*)&hp1;
    lo.x = *(uint32_t*)&lp0; lo.y = *(uint32_t*)&lp1;
}

// ---------------------------------------------------------------------------
// transpose W[K][N] -> Wt[N][K] with bf16 hi/lo split (weights only; small)
// ---------------------------------------------------------------------------
__global__ void tsplit_kernel(const float* __restrict__ W,
                              __nv_bfloat16* __restrict__ thi,
                              __nv_bfloat16* __restrict__ tlo,
                              int Kd, int Nd)
{
    int idx = blockIdx.x * blockDim.x + threadIdx.x;
    if (idx >= Kd * Nd) return;
    int k = idx / Nd, n = idx % Nd;
    float v = W[idx];
    __nv_bfloat16 h = __float2bfloat16_rn(v);
    thi[(size_t)n * Kd + k] = h;
    tlo[(size_t)n * Kd + k] = __float2bfloat16_rn(v - __bfloat162float(h));
}

__global__ void concat_bias_kernel(const float* __restrict__ b0,
                                   const float* __restrict__ b1,
                                   float* __restrict__ dst)
{
    int i = threadIdx.x;
    if (i < 256) dst[i] = b0[i];
    else if (i < 384) dst[i] = b1[i - 256];
}

// ---------------------------------------------------------------------------
// mma.sync bf16x3 GEMM, fp32 A in, double-buffered.
// C[M,N] = A_f32[M,K=256] @ (Bhi+Blo)^T[N][K] + bias. CTA 128x128, 8 warps.
// smem: 2 stages x (A_hi 16K | A_lo 16K | B_hi 16K | B_lo 16K) = 128KB
// ---------------------------------------------------------------------------
__global__ __launch_bounds__(256, 1)
void gemm_f32_bf16x3(const float* __restrict__ A,
                     const __nv_bfloat16* __restrict__ Bhi,
                     const __nv_bfloat16* __restrict__ Blo,
                     const float* __restrict__ bias,
                     float* __restrict__ C,
                     int M, int N)
{
    extern __shared__ char smem[];
    const uint32_t sbase = smem_u32(smem);

    const int tid = threadIdx.x, lane = tid & 31, wid = tid >> 5;
    const int brow = blockIdx.y * 128, bcol = blockIdx.x * 128;
    const int wr = (wid >> 2) * 64;
    const int wc = (wid & 3) * 32;

    float acc[4][4][4];
#pragma unroll
    for (int i = 0; i < 4; i++)
#pragma unroll
        for (int j = 0; j < 4; j++)
#pragma unroll
            for (int k = 0; k < 4; k++) acc[i][j][k] = 0.f;

    // A-load mapping: t = i*256 + tid, t in [0,2048): row = t>>4, jc = t&15 (float4 col)
    // B cp.async mapping: t = i*256 + tid, t in [0,1024): row = t>>3, j = t&7 (16B col)

    // ldmatrix per-lane address components
    const int a_r  = wr + (lane & 15);
    const int a_kx = (lane >> 4) << 4;
    const int b_r0 = wc + (lane & 7) + ((lane >> 4) << 3);
    const int b_kx = ((lane >> 3) & 1) << 4;

    float4 aPre[8];

    // ---- prologue: load chunk 0 ----
    {
        // B chunk 0 via cp.async
        const uint32_t sb_hi = sbase + 32768u, sb_lo = sbase + 49152u;
#pragma unroll
        for (int i = 0; i < 4; i++) {
            int t = i * 256 + tid;
            int r = t >> 3, j = t & 7;
            uint32_t d = SMEM_SWIZZLE_128B((uint32_t)(r * 128 + j * 16));
            size_t src = (size_t)(bcol + r) * KDIM + j * 8;
            cp16(sb_hi + d, Bhi + src);
            cp16(sb_lo + d, Blo + src);
        }
        cp_commit();
        // A chunk 0 via LDG
#pragma unroll
        for (int i = 0; i < 8; i++) {
            int t = i * 256 + tid;
            int r = t >> 4, jc = t & 15;
            aPre[i] = (brow + r < M)
                ? __ldg((const float4*)(A + (size_t)(brow + r) * KDIM + jc * 4))
                : make_float4(0.f, 0.f, 0.f, 0.f);
        }
        // store A chunk 0
#pragma unroll
        for (int i = 0; i < 8; i++) {
            int t = i * 256 + tid;
            int r = t >> 4, jc = t & 15;
            uint32_t d = SMEM_SWIZZLE_128B((uint32_t)(r * 128 + (jc >> 1) * 16)) + (jc & 1) * 8;
            uint2 ho, lo;
            split4(aPre[i], ho, lo);
            *(uint2*)(smem + d) = ho;
            *(uint2*)(smem + 16384u + d) = lo;
        }
        cp_wait0();
        __syncthreads();
    }

    const int nk = KDIM / 64;   // 4
    for (int kc = 0; kc < nk; kc++) {
        const int cur = kc & 1, nxt = cur ^ 1;
        const uint32_t scur = sbase + (uint32_t)cur * 65536u;
        const bool hn = (kc + 1) < nk;

        if (hn) {
            // issue next B cp.async + next A LDGs (overlap with compute below)
            const uint32_t snb = sbase + (uint32_t)nxt * 65536u;
#pragma unroll
            for (int i = 0; i < 4; i++) {
                int t = i * 256 + tid;
                int r = t >> 3, j = t & 7;
                uint32_t d = SMEM_SWIZZLE_128B((uint32_t)(r * 128 + j * 16));
                size_t src = (size_t)(bcol + r) * KDIM + (kc + 1) * 64 + j * 8;
                cp16(snb + 32768u + d, Bhi + src);
                cp16(snb + 49152u + d, Blo + src);
            }
            cp_commit();
#pragma unroll
            for (int i = 0; i < 8; i++) {
                int t = i * 256 + tid;
                int r = t >> 4, jc = t & 15;
                aPre[i] = (brow + r < M)
                    ? __ldg((const float4*)(A + (size_t)(brow + r) * KDIM + (kc + 1) * 64 + jc * 4))
                    : make_float4(0.f, 0.f, 0.f, 0.f);
            }
        }

        // ---- compute on stage cur ----
        const uint32_t sa_hi = scur, sa_lo = scur + 16384u;
        const uint32_t sb_hi = scur + 32768u, sb_lo = scur + 49152u;
#pragma unroll
        for (int kk = 0; kk < 4; kk++) {
            const uint32_t kbA = (uint32_t)(kk * 32 + a_kx);
            const uint32_t kbB = (uint32_t)(kk * 32 + b_kx);

            uint32_t ahi[4][4], bhi[4][2];
#pragma unroll
            for (int mi = 0; mi < 4; mi++)
                ldm_x4(ahi[mi], sa_hi + SMEM_SWIZZLE_128B((uint32_t)((a_r + mi * 16) * 128) + kbA));
#pragma unroll
            for (int nj = 0; nj < 2; nj++) {
                uint32_t rr[4];
                ldm_x4(rr, sb_hi + SMEM_SWIZZLE_128B((uint32_t)((b_r0 + nj * 16) * 128) + kbB));
                bhi[nj * 2][0] = rr[0]; bhi[nj * 2][1] = rr[1];
                bhi[nj * 2 + 1][0] = rr[2]; bhi[nj * 2 + 1][1] = rr[3];
            }
#pragma unroll
            for (int mi = 0; mi < 4; mi++)
#pragma unroll
                for (int ni = 0; ni < 4; ni++)
                    mma16816(acc[mi][ni], ahi[mi], bhi[ni]);

            uint32_t blo[4][2];
#pragma unroll
            for (int nj = 0; nj < 2; nj++) {
                uint32_t rr[4];
                ldm_x4(rr, sb_lo + SMEM_SWIZZLE_128B((uint32_t)((b_r0 + nj * 16) * 128) + kbB));
                blo[nj * 2][0] = rr[0]; blo[nj * 2][1] = rr[1];
                blo[nj * 2 + 1][0] = rr[2]; blo[nj * 2 + 1][1] = rr[3];
            }
#pragma unroll
            for (int mi = 0; mi < 4; mi++)
#pragma unroll
                for (int ni = 0; ni < 4; ni++)
                    mma16816(acc[mi][ni], ahi[mi], blo[ni]);

            uint32_t alo[4][4];
#pragma unroll
            for (int mi = 0; mi < 4; mi++)
                ldm_x4(alo[mi], sa_lo + SMEM_SWIZZLE_128B((uint32_t)((a_r + mi * 16) * 128) + kbA));
#pragma unroll
            for (int mi = 0; mi < 4; mi++)
#pragma unroll
                for (int ni = 0; ni < 4; ni++)
                    mma16816(acc[mi][ni], alo[mi], bhi[ni]);
        }

        if (hn) {
            // store prefetched A into next stage, wait B, sync
            const uint32_t snb = sbase + (uint32_t)nxt * 65536u;
#pragma unroll
            for (int i = 0; i < 8; i++) {
                int t = i * 256 + tid;
                int r = t >> 4, jc = t & 15;
                uint32_t d = SMEM_SWIZZLE_128B((uint32_t)(r * 128 + (jc >> 1) * 16)) + (jc & 1) * 8;
                uint2 ho, lo;
                split4(aPre[i], ho, lo);
                *(uint2*)(smem + (size_t)(snb - sbase) + d) = ho;
                *(uint2*)(smem + (size_t)(snb - sbase) + 16384u + d) = lo;
            }
            cp_wait0();
            __syncthreads();
        }
    }

    // ---- epilogue: bias + float2 stores ----
    const int row0 = brow + wr + (lane >> 2);
#pragma unroll
    for (int ni = 0; ni < 4; ni++) {
        int col = bcol + wc + ni * 8 + (lane & 3) * 2;
        float2 bb = *(const float2*)&bias[col];
#pragma unroll
        for (int mi = 0; mi < 4; mi++) {
            int r0 = row0 + mi * 16;
            if (r0 < M) {
                float2 o;
                o.x = acc[mi][ni][0] + bb.x;
                o.y = acc[mi][ni][1] + bb.y;
                *(float2*)(C + (size_t)r0 * N + col) = o;
            }
            int r1 = r0 + 8;
            if (r1 < M) {
                float2 o;
                o.x = acc[mi][ni][2] + bb.x;
                o.y = acc[mi][ni][3] + bb.y;
                *(float2*)(C + (size_t)r1 * N + col) = o;
            }
        }
    }
}

// ---------------------------------------------------------------------------
// Fused softmax + bilinear sampling. Owner-lane precompute:
// each lane computes coefs + packed positions for its 2 points once; main
// loop shuffles 6 words per point and does only gathers + FMAs.
// ---------------------------------------------------------------------------
__global__ __launch_bounds__(256)
void msda_sample_kernel(const float* __restrict__ ref)
{
    int warp_global = blockIdx.x * (blockDim.x >> 5) + (threadIdx.x >> 5);
    if (warp_global >= Bb * LQ * 2) return;
    int lane = threadIdx.x & 31;
    int g = lane >> 3;
    int r = lane & 7;

    int hpair = warp_global & 1;
    int bq    = warp_global >> 1;
    int b     = bq / LQ;
    int hh    = hpair * 4 + g;

    // ---- softmax over 16 logits; lane r holds logits [2r, 2r+1] ----
    const float2* awp = (const float2*)(g_offaw + (size_t)bq * 384 + 256 + hh * 16);
    float2 lg = awp[r];
    float m = fmaxf(lg.x, lg.y);
#pragma unroll
    for (int o = 4; o > 0; o >>= 1) m = fmaxf(m, __shfl_xor_sync(0xffffffffu, m, o));
    float e0 = __expf(lg.x - m);
    float e1 = __expf(lg.y - m);
    float s = e0 + e1;
#pragma unroll
    for (int o = 4; o > 0; o >>= 1) s += __shfl_xor_sync(0xffffffffu, s, o);
    float inv = 1.f / s;
    float w0 = e0 * inv;
    float w1 = e1 * inv;

    // ---- offsets for this lane's 2 points ----
    const float4* offp = (const float4*)(g_offaw + (size_t)bq * 384 + hh * 32);
    float4 off4 = offp[r];

    // ---- owner-lane precompute: level geometry from r ----
    int l  = r >> 1;
    int HW = 80 >> l;
    int start = (l > 0 ? 6400 : 0) + (l > 1 ? 1600 : 0) + (l > 2 ? 400 : 0);
    float fHW = (float)HW;
    float2 rxy = __ldg((const float2*)ref + (size_t)bq * 4 + l);

    float cA[4], cB[4];
    uint32_t pkA0, pkA1, pkB0, pkB1;
#pragma unroll
    for (int pt = 0; pt < 2; pt++) {
        float ox = pt ? off4.z : off4.x;
        float oy = pt ? off4.w : off4.y;
        float aw = pt ? w1 : w0;

        float x = fmaf(rxy.x, fHW, ox - 0.5f);
        float y = fmaf(rxy.y, fHW, oy - 0.5f);
        float x0f = floorf(x), y0f = floorf(y);
        float wx = x - x0f, wy = y - y0f;
        int x0 = (int)x0f, y0 = (int)y0f;
        int x1 = x0 + 1,   y1 = y0 + 1;

        float vx0 = (x0 >= 0 && x0 < HW) ? 1.f : 0.f;
        float vx1 = (x1 >= 0 && x1 < HW) ? 1.f : 0.f;
        float vy0 = (y0 >= 0 && y0 < HW) ? 1.f : 0.f;
        float vy1 = (y1 >= 0 && y1 < HW) ? 1.f : 0.f;

        int cx0 = min(max(x0, 0), HW - 1);
        int cx1 = min(max(x1, 0), HW - 1);
        int cy0 = min(max(y0, 0), HW - 1);
        int cy1 = min(max(y1, 0), HW - 1);

        uint32_t p00 = (uint32_t)(start + cy0 * HW + cx0);
        uint32_t p01 = (uint32_t)(start + cy0 * HW + cx1);
        uint32_t p10 = (uint32_t)(start + cy1 * HW + cx0);
        uint32_t p11 = (uint32_t)(start + cy1 * HW + cx1);

        float wx1 = 1.f - wx, wy1 = 1.f - wy;
        float c0 = aw * wx1 * wy1 * vx0 * vy0;
        float c1 = aw * wx  * wy1 * vx1 * vy0;
        float c2 = aw * wx1 * wy  * vx0 * vy1;
        float c3 = aw * wx  * wy  * vx1 * vy1;

        if (pt == 0) {
            cA[0] = c0; cA[1] = c1; cA[2] = c2; cA[3] = c3;
            pkA0 = p00 | (p01 << 16); pkA1 = p10 | (p11 << 16);
        } else {
            cB[0] = c0; cB[1] = c1; cB[2] = c2; cB[3] = c3;
            pkB0 = p00 | (p01 << 16); pkB1 = p10 | (p11 << 16);
        }
    }

    // ---- main loop: 8 owner lanes x 2 points, gather + FMA only ----
    const float* pbase = g_v + (size_t)b * LVTOT * Ee + hh * HEAD_DIM + r * 4;
    float4 acc = make_float4(0.f, 0.f, 0.f, 0.f);

#pragma unroll
    for (int j = 0; j < 8; j++) {
        int src = (g << 3) + j;
#pragma unroll
        for (int pt = 0; pt < 2; pt++) {
            float c0 = __shfl_sync(0xffffffffu, pt ? cB[0] : cA[0], src);
            float c1 = __shfl_sync(0xffffffffu, pt ? cB[1] : cA[1], src);
            float c2 = __shfl_sync(0xffffffffu, pt ? cB[2] : cA[2], src);
            float c3 = __shfl_sync(0xffffffffu, pt ? cB[3] : cA[3], src);
            uint32_t q0 = __shfl_sync(0xffffffffu, pt ? pkB0 : pkA0, src);
            uint32_t q1 = __shfl_sync(0xffffffffu, pt ? pkB1 : pkA1, src);

            uint32_t i00 = q0 & 0xffffu, i01 = q0 >> 16;
            uint32_t i10 = q1 & 0xffffu, i11 = q1 >> 16;

            float4 v00 = __ldg((const float4*)(pbase + (size_t)i00 * Ee));
            float4 v01 = __ldg((const float4*)(pbase + (size_t)i01 * Ee));
            float4 v10 = __ldg((const float4*)(pbase + (size_t)i10 * Ee));
            float4 v11 = __ldg((const float4*)(pbase + (size_t)i11 * Ee));

            acc.x = fmaf(c0, v00.x, fmaf(c1, v01.x, fmaf(c2, v10.x, fmaf(c3, v11.x, acc.x))));
            acc.y = fmaf(c0, v00.y, fmaf(c1, v01.y, fmaf(c2, v10.y, fmaf(c3, v11.y, acc.y))));
            acc.z = fmaf(c0, v00.z, fmaf(c1, v01.z, fmaf(c2, v10.z, fmaf(c3, v11.z, acc.z))));
            acc.w = fmaf(c0, v00.w, fmaf(c1, v01.w, fmaf(c2, v10.w, fmaf(c3, v11.w, acc.w))));
        }
    }

    *(float4*)(g_tmp + (size_t)bq * Ee + hh * HEAD_DIM + r * 4) = acc;
}

// ---------------------------------------------------------------------------
extern "C" void kernel_launch(void* const* d_in, const int* in_sizes, int n_in,
                              void* d_out, int out_size)
{
    const float* query = (const float*)d_in[0];
    const float* ref   = (const float*)d_in[1];
    const float* value = (const float*)d_in[2];
    const float* Wv    = (const float*)d_in[4];
    const float* bv    = (const float*)d_in[5];
    const float* Woff  = (const float*)d_in[6];
    const float* boff  = (const float*)d_in[7];
    const float* Wattn = (const float*)d_in[8];
    const float* battn = (const float*)d_in[9];
    const float* Wo    = (const float*)d_in[10];
    const float* bo    = (const float*)d_in[11];
    float* out = (float*)d_out;

    float *pv, *poffaw, *ptmp, *pbc;
    __nv_bfloat16 *pwhi, *pwlo;
    cudaGetSymbolAddress((void**)&pv,     g_v);
    cudaGetSymbolAddress((void**)&poffaw, g_offaw);
    cudaGetSymbolAddress((void**)&ptmp,   g_tmp);
    cudaGetSymbolAddress((void**)&pbc,    g_bias_comb);
    cudaGetSymbolAddress((void**)&pwhi,   g_wt_hi);
    cudaGetSymbolAddress((void**)&pwlo,   g_wt_lo);

    cudaFuncSetAttribute(gemm_f32_bf16x3,
                         cudaFuncAttributeMaxDynamicSharedMemorySize, 131072);

    // ---- weight transforms (small) ----
    tsplit_kernel<<<(256 * 256 + 255) / 256, 256>>>(Wv,   pwhi + WT_WV, pwlo + WT_WV, 256, 256);
    tsplit_kernel<<<(256 * 256 + 255) / 256, 256>>>(Woff, pwhi + WT_COMB, pwlo + WT_COMB, 256, 256);
    tsplit_kernel<<<(256 * 128 + 255) / 256, 256>>>(Wattn,
        pwhi + WT_COMB + 256 * 256, pwlo + WT_COMB + 256 * 256, 256, 128);
    tsplit_kernel<<<(256 * 256 + 255) / 256, 256>>>(Wo,   pwhi + WT_WO, pwlo + WT_WO, 256, 256);
    concat_bias_kernel<<<1, 384>>>(boff, battn, pbc);

    // ---- GEMM 1: g_v = value @ Wv + bv ----
    {
        dim3 grid(2, (MV + 127) / 128);
        gemm_f32_bf16x3<<<grid, 256, 131072>>>(value, pwhi + WT_WV, pwlo + WT_WV,
                                               bv, pv, MV, 256);
    }
    // ---- GEMM 2 (fused): g_offaw = query @ [Woff | Wattn] + [boff | battn] ----
    {
        dim3 grid(3, (MQ + 127) / 128);
        gemm_f32_bf16x3<<<grid, 256, 131072>>>(query, pwhi + WT_COMB, pwlo + WT_COMB,
                                               pbc, poffaw, MQ, 384);
    }
    // ---- sampler ----
    {
        int total_warps = Bb * LQ * 2;
        int blocks = (total_warps + 7) / 8;
        msda_sample_kernel<<<blocks, 256>>>(ref);
    }
    // ---- GEMM 3: out = g_tmp @ Wo + bo ----
    {
        dim3 grid(2, (MQ + 127) / 128);
        gemm_f32_bf16x3<<<grid, 256, 131072>>>(ptmp, pwhi + WT_WO, pwlo + WT_WO,
                                               bo, out, MQ, 256);
    }
}

// round 7
// speedup vs baseline: 3.4625x; 1.0700x over previous
#include <cuda_runtime.h>
#include <cuda_bf16.h>
#include <math.h>
#include <stdint.h>

#define Bb 4
#define LQ 8400
#define Ee 256
#define HEADS 8
#define LEVELS 4
#define POINTS 4
#define HEAD_DIM 32
#define LVTOT 8500
#define KDIM 256

#define MQ (Bb * LQ)     // 33600
#define MV (Bb * LVTOT)  // 34000

// ---------------- scratch (device globals; no allocation allowed) ----------
__device__ float g_v[MV * Ee];            // value @ Wv + bv (f32, sampler input)
__device__ float g_offaw[MQ * 384];       // [off(256) | aw(128)] fused GEMM output
__device__ float g_tmp[MQ * Ee];          // sampler output (f32)
__device__ float g_bias_comb[384];

// transposed weights [N][K] bf16 hi/lo
#define WT_WV    0
#define WT_COMB  65536
#define WT_WO    163840
#define WT_TOTAL 229376
__device__ __nv_bfloat16 g_wt_hi[WT_TOTAL];
__device__ __nv_bfloat16 g_wt_lo[WT_TOTAL];

// ---------------- helpers ----------------------------------------------
#define SMEM_SWIZZLE_128B(byte_offset) \
    ((byte_offset) ^ (((byte_offset) >> 3) & 0x70))

__device__ __forceinline__ uint32_t smem_u32(const void* p) {
    uint32_t a;
    asm("{ .reg .u64 t; cvta.to.shared.u64 t, %1; cvt.u32.u64 %0, t; }"
        : "=r"(a) : "l"(p));
    return a;
}

__device__ __forceinline__ void cp16(uint32_t dst, const void* src) {
    asm volatile("cp.async.cg.shared.global [%0], [%1], 16;"
                 :: "r"(dst), "l"(src));
}

__device__ __forceinline__ void cp_commit() {
    asm volatile("cp.async.commit_group;" ::: "memory");
}
__device__ __forceinline__ void cp_wait0() {
    asm volatile("cp.async.wait_group 0;" ::: "memory");
}

__device__ __forceinline__ void ldm_x4(uint32_t* r, uint32_t addr) {
    asm volatile("ldmatrix.sync.aligned.m8n8.x4.shared.b16 {%0,%1,%2,%3}, [%4];"
                 : "=r"(r[0]), "=r"(r[1]), "=r"(r[2]), "=r"(r[3]) : "r"(addr));
}

__device__ __forceinline__ void mma16816(float* c, const uint32_t* a, const uint32_t* b) {
    asm volatile("mma.sync.aligned.m16n8k16.row.col.f32.bf16.bf16.f32 "
                 "{%0,%1,%2,%3}, {%4,%5,%6,%7}, {%8,%9}, {%0,%1,%2,%3};"
                 : "+f"(c[0]), "+f"(c[1]), "+f"(c[2]), "+f"(c[3])
                 : "r"(a[0]), "r"(a[1]), "r"(a[2]), "r"(a[3]),
                   "r"(b[0]), "r"(b[1]));
}

__device__ __forceinline__ void split4(float4 v, uint2& ho, uint2& lo) {
    __nv_bfloat16 h0 = __float2bfloat16_rn(v.x);
    __nv_bfloat16 h1 = __float2bfloat16_rn(v.y);
    __nv_bfloat16 h2 = __float2bfloat16_rn(v.z);
    __nv_bfloat16 h3 = __float2bfloat16_rn(v.w);
    __nv_bfloat16 l0 = __float2bfloat16_rn(v.x - __bfloat162float(h0));
    __nv_bfloat16 l1 = __float2bfloat16_rn(v.y - __bfloat162float(h1));
    __nv_bfloat16 l2 = __float2bfloat16_rn(v.z - __bfloat162float(h2));
    __nv_bfloat16 l3 = __float2bfloat16_rn(v.w - __bfloat162float(h3));
    __nv_bfloat162 hp0; hp0.x = h0; hp0.y = h1;
    __nv_bfloat162 hp1; hp1.x = h2; hp1.y = h3;
    __nv_bfloat162 lp0; lp0.x = l0; lp0.y = l1;
    __nv_bfloat162 lp1; lp1.x = l2; lp1.y = l3;
    ho.x = *(uint32_t*)&hp0; ho.y = *(uint32_t*)&hp1;
    lo.x = *(uint32_t*)&lp0; lo.y = *(uint32_t*)&lp1;
}

// ---------------------------------------------------------------------------
// ONE prep kernel: all 4 weight transposes+splits + bias concat.
// ---------------------------------------------------------------------------
__global__ void prep_weights_kernel(const float* __restrict__ Wv,
                                    const float* __restrict__ Woff,
                                    const float* __restrict__ Wattn,
                                    const float* __restrict__ Wo,
                                    const float* __restrict__ boff,
                                    const float* __restrict__ battn)
{
    int idx = blockIdx.x * blockDim.x + threadIdx.x;
    if (idx < 384)
        g_bias_comb[idx] = (idx < 256) ? boff[idx] : battn[idx - 256];
    if (idx >= WT_TOTAL) return;

    const float* W;
    int Nd, out, t = idx;
    if (t < 65536)        { W = Wv;    Nd = 256; out = WT_WV; }
    else if (t < 131072)  { W = Woff;  Nd = 256; out = WT_COMB;          t -= 65536; }
    else if (t < 163840)  { W = Wattn; Nd = 128; out = WT_COMB + 65536;  t -= 131072; }
    else                  { W = Wo;    Nd = 256; out = WT_WO;            t -= 163840; }

    int k = t / Nd, n = t % Nd;
    float v = W[k * Nd + n];            // W is [K=256][Nd]
    __nv_bfloat16 h = __float2bfloat16_rn(v);
    g_wt_hi[out + n * 256 + k] = h;
    g_wt_lo[out + n * 256 + k] = __float2bfloat16_rn(v - __bfloat162float(h));
}

// ---------------------------------------------------------------------------
// mma.sync bf16x3 GEMM, fp32 A in, double-buffered. 512 threads, 16 warps,
// warp tile 32x32 (4x4 warp grid over 128x128 CTA tile).
// smem: 2 stages x (A_hi 16K | A_lo 16K | B_hi 16K | B_lo 16K) = 128KB
// ---------------------------------------------------------------------------
__global__ __launch_bounds__(512, 1)
void gemm_f32_bf16x3(const float* __restrict__ A,
                     const __nv_bfloat16* __restrict__ Bhi,
                     const __nv_bfloat16* __restrict__ Blo,
                     const float* __restrict__ bias,
                     float* __restrict__ C,
                     int M, int N)
{
    extern __shared__ char smem[];
    const uint32_t sbase = smem_u32(smem);

    const int tid = threadIdx.x, lane = tid & 31, wid = tid >> 5;
    const int brow = blockIdx.y * 128, bcol = blockIdx.x * 128;
    const int wr = (wid >> 2) * 32;   // warp row base (0,32,64,96)
    const int wc = (wid & 3) * 32;    // warp col base (0,32,64,96)

    float acc[2][4][4];
#pragma unroll
    for (int i = 0; i < 2; i++)
#pragma unroll
        for (int j = 0; j < 4; j++)
#pragma unroll
            for (int k = 0; k < 4; k++) acc[i][j][k] = 0.f;

    // ldmatrix per-lane address components
    const int a_r  = wr + (lane & 15);
    const int a_kx = (lane >> 4) << 4;
    const int b_r0 = wc + (lane & 7) + ((lane >> 4) << 3);
    const int b_kx = ((lane >> 3) & 1) << 4;

    float4 aPre[4];

    // ---- prologue: chunk 0 ----
    {
        const uint32_t sb_hi = sbase + 32768u, sb_lo = sbase + 49152u;
#pragma unroll
        for (int i = 0; i < 2; i++) {
            int t = i * 512 + tid;
            int r = t >> 3, j = t & 7;
            uint32_t d = SMEM_SWIZZLE_128B((uint32_t)(r * 128 + j * 16));
            size_t src = (size_t)(bcol + r) * KDIM + j * 8;
            cp16(sb_hi + d, Bhi + src);
            cp16(sb_lo + d, Blo + src);
        }
        cp_commit();
#pragma unroll
        for (int i = 0; i < 4; i++) {
            int t = i * 512 + tid;
            int r = t >> 4, jc = t & 15;
            aPre[i] = (brow + r < M)
                ? __ldg((const float4*)(A + (size_t)(brow + r) * KDIM + jc * 4))
                : make_float4(0.f, 0.f, 0.f, 0.f);
        }
#pragma unroll
        for (int i = 0; i < 4; i++) {
            int t = i * 512 + tid;
            int r = t >> 4, jc = t & 15;
            uint32_t d = SMEM_SWIZZLE_128B((uint32_t)(r * 128 + (jc >> 1) * 16)) + (jc & 1) * 8;
            uint2 ho, lo;
            split4(aPre[i], ho, lo);
            *(uint2*)(smem + d) = ho;
            *(uint2*)(smem + 16384u + d) = lo;
        }
        cp_wait0();
        __syncthreads();
    }

    const int nk = KDIM / 64;   // 4
    for (int kc = 0; kc < nk; kc++) {
        const int cur = kc & 1, nxt = cur ^ 1;
        const uint32_t scur = sbase + (uint32_t)cur * 65536u;
        const bool hn = (kc + 1) < nk;

        if (hn) {
            const uint32_t snb = sbase + (uint32_t)nxt * 65536u;
#pragma unroll
            for (int i = 0; i < 2; i++) {
                int t = i * 512 + tid;
                int r = t >> 3, j = t & 7;
                uint32_t d = SMEM_SWIZZLE_128B((uint32_t)(r * 128 + j * 16));
                size_t src = (size_t)(bcol + r) * KDIM + (kc + 1) * 64 + j * 8;
                cp16(snb + 32768u + d, Bhi + src);
                cp16(snb + 49152u + d, Blo + src);
            }
            cp_commit();
#pragma unroll
            for (int i = 0; i < 4; i++) {
                int t = i * 512 + tid;
                int r = t >> 4, jc = t & 15;
                aPre[i] = (brow + r < M)
                    ? __ldg((const float4*)(A + (size_t)(brow + r) * KDIM + (kc + 1) * 64 + jc * 4))
                    : make_float4(0.f, 0.f, 0.f, 0.f);
            }
        }

        // ---- compute on stage cur ----
        const uint32_t sa_hi = scur, sa_lo = scur + 16384u;
        const uint32_t sb_hi = scur + 32768u, sb_lo = scur + 49152u;
#pragma unroll
        for (int kk = 0; kk < 4; kk++) {
            const uint32_t kbA = (uint32_t)(kk * 32 + a_kx);
            const uint32_t kbB = (uint32_t)(kk * 32 + b_kx);

            uint32_t ahi[2][4], bhi[4][2];
#pragma unroll
            for (int mi = 0; mi < 2; mi++)
                ldm_x4(ahi[mi], sa_hi + SMEM_SWIZZLE_128B((uint32_t)((a_r + mi * 16) * 128) + kbA));
#pragma unroll
            for (int nj = 0; nj < 2; nj++) {
                uint32_t rr[4];
                ldm_x4(rr, sb_hi + SMEM_SWIZZLE_128B((uint32_t)((b_r0 + nj * 16) * 128) + kbB));
                bhi[nj * 2][0] = rr[0]; bhi[nj * 2][1] = rr[1];
                bhi[nj * 2 + 1][0] = rr[2]; bhi[nj * 2 + 1][1] = rr[3];
            }
#pragma unroll
            for (int mi = 0; mi < 2; mi++)
#pragma unroll
                for (int ni = 0; ni < 4; ni++)
                    mma16816(acc[mi][ni], ahi[mi], bhi[ni]);

            uint32_t blo[4][2];
#pragma unroll
            for (int nj = 0; nj < 2; nj++) {
                uint32_t rr[4];
                ldm_x4(rr, sb_lo + SMEM_SWIZZLE_128B((uint32_t)((b_r0 + nj * 16) * 128) + kbB));
                blo[nj * 2][0] = rr[0]; blo[nj * 2][1] = rr[1];
                blo[nj * 2 + 1][0] = rr[2]; blo[nj * 2 + 1][1] = rr[3];
            }
#pragma unroll
            for (int mi = 0; mi < 2; mi++)
#pragma unroll
                for (int ni = 0; ni < 4; ni++)
                    mma16816(acc[mi][ni], ahi[mi], blo[ni]);

            uint32_t alo[2][4];
#pragma unroll
            for (int mi = 0; mi < 2; mi++)
                ldm_x4(alo[mi], sa_lo + SMEM_SWIZZLE_128B((uint32_t)((a_r + mi * 16) * 128) + kbA));
#pragma unroll
            for (int mi = 0; mi < 2; mi++)
#pragma unroll
                for (int ni = 0; ni < 4; ni++)
                    mma16816(acc[mi][ni], alo[mi], bhi[ni]);
        }

        if (hn) {
            const uint32_t snb_off = (uint32_t)nxt * 65536u;
#pragma unroll
            for (int i = 0; i < 4; i++) {
                int t = i * 512 + tid;
                int r = t >> 4, jc = t & 15;
                uint32_t d = SMEM_SWIZZLE_128B((uint32_t)(r * 128 + (jc >> 1) * 16)) + (jc & 1) * 8;
                uint2 ho, lo;
                split4(aPre[i], ho, lo);
                *(uint2*)(smem + snb_off + d) = ho;
                *(uint2*)(smem + snb_off + 16384u + d) = lo;
            }
            cp_wait0();
            __syncthreads();
        }
    }

    // ---- epilogue: bias + float2 stores ----
    const int row0 = brow + wr + (lane >> 2);
#pragma unroll
    for (int ni = 0; ni < 4; ni++) {
        int col = bcol + wc + ni * 8 + (lane & 3) * 2;
        float2 bb = *(const float2*)&bias[col];
#pragma unroll
        for (int mi = 0; mi < 2; mi++) {
            int r0 = row0 + mi * 16;
            if (r0 < M) {
                float2 o;
                o.x = acc[mi][ni][0] + bb.x;
                o.y = acc[mi][ni][1] + bb.y;
                *(float2*)(C + (size_t)r0 * N + col) = o;
            }
            int r1 = r0 + 8;
            if (r1 < M) {
                float2 o;
                o.x = acc[mi][ni][2] + bb.x;
                o.y = acc[mi][ni][3] + bb.y;
                *(float2*)(C + (size_t)r1 * N + col) = o;
            }
        }
    }
}

// ---------------------------------------------------------------------------
// Fused softmax + bilinear sampling (owner-lane precompute, unchanged).
// ---------------------------------------------------------------------------
__global__ __launch_bounds__(256)
void msda_sample_kernel(const float* __restrict__ ref)
{
    int warp_global = blockIdx.x * (blockDim.x >> 5) + (threadIdx.x >> 5);
    if (warp_global >= Bb * LQ * 2) return;
    int lane = threadIdx.x & 31;
    int g = lane >> 3;
    int r = lane & 7;

    int hpair = warp_global & 1;
    int bq    = warp_global >> 1;
    int b     = bq / LQ;
    int hh    = hpair * 4 + g;

    const float2* awp = (const float2*)(g_offaw + (size_t)bq * 384 + 256 + hh * 16);
    float2 lg = awp[r];
    float m = fmaxf(lg.x, lg.y);
#pragma unroll
    for (int o = 4; o > 0; o >>= 1) m = fmaxf(m, __shfl_xor_sync(0xffffffffu, m, o));
    float e0 = __expf(lg.x - m);
    float e1 = __expf(lg.y - m);
    float s = e0 + e1;
#pragma unroll
    for (int o = 4; o > 0; o >>= 1) s += __shfl_xor_sync(0xffffffffu, s, o);
    float inv = 1.f / s;
    float w0 = e0 * inv;
    float w1 = e1 * inv;

    const float4* offp = (const float4*)(g_offaw + (size_t)bq * 384 + hh * 32);
    float4 off4 = offp[r];

    int l  = r >> 1;
    int HW = 80 >> l;
    int start = (l > 0 ? 6400 : 0) + (l > 1 ? 1600 : 0) + (l > 2 ? 400 : 0);
    float fHW = (float)HW;
    float2 rxy = __ldg((const float2*)ref + (size_t)bq * 4 + l);

    float cA[4], cB[4];
    uint32_t pkA0, pkA1, pkB0, pkB1;
#pragma unroll
    for (int pt = 0; pt < 2; pt++) {
        float ox = pt ? off4.z : off4.x;
        float oy = pt ? off4.w : off4.y;
        float aw = pt ? w1 : w0;

        float x = fmaf(rxy.x, fHW, ox - 0.5f);
        float y = fmaf(rxy.y, fHW, oy - 0.5f);
        float x0f = floorf(x), y0f = floorf(y);
        float wx = x - x0f, wy = y - y0f;
        int x0 = (int)x0f, y0 = (int)y0f;
        int x1 = x0 + 1,   y1 = y0 + 1;

        float vx0 = (x0 >= 0 && x0 < HW) ? 1.f : 0.f;
        float vx1 = (x1 >= 0 && x1 < HW) ? 1.f : 0.f;
        float vy0 = (y0 >= 0 && y0 < HW) ? 1.f : 0.f;
        float vy1 = (y1 >= 0 && y1 < HW) ? 1.f : 0.f;

        int cx0 = min(max(x0, 0), HW - 1);
        int cx1 = min(max(x1, 0), HW - 1);
        int cy0 = min(max(y0, 0), HW - 1);
        int cy1 = min(max(y1, 0), HW - 1);

        uint32_t p00 = (uint32_t)(start + cy0 * HW + cx0);
        uint32_t p01 = (uint32_t)(start + cy0 * HW + cx1);
        uint32_t p10 = (uint32_t)(start + cy1 * HW + cx0);
        uint32_t p11 = (uint32_t)(start + cy1 * HW + cx1);

        float wx1 = 1.f - wx, wy1 = 1.f - wy;
        float c0 = aw * wx1 * wy1 * vx0 * vy0;
        float c1 = aw * wx  * wy1 * vx1 * vy0;
        float c2 = aw * wx1 * wy  * vx0 * vy1;
        float c3 = aw * wx  * wy  * vx1 * vy1;

        if (pt == 0) {
            cA[0] = c0; cA[1] = c1; cA[2] = c2; cA[3] = c3;
            pkA0 = p00 | (p01 << 16); pkA1 = p10 | (p11 << 16);
        } else {
            cB[0] = c0; cB[1] = c1; cB[2] = c2; cB[3] = c3;
            pkB0 = p00 | (p01 << 16); pkB1 = p10 | (p11 << 16);
        }
    }

    const float* pbase = g_v + (size_t)b * LVTOT * Ee + hh * HEAD_DIM + r * 4;
    float4 acc = make_float4(0.f, 0.f, 0.f, 0.f);

#pragma unroll
    for (int j = 0; j < 8; j++) {
        int src = (g << 3) + j;
#pragma unroll
        for (int pt = 0; pt < 2; pt++) {
            float c0 = __shfl_sync(0xffffffffu, pt ? cB[0] : cA[0], src);
            float c1 = __shfl_sync(0xffffffffu, pt ? cB[1] : cA[1], src);
            float c2 = __shfl_sync(0xffffffffu, pt ? cB[2] : cA[2], src);
            float c3 = __shfl_sync(0xffffffffu, pt ? cB[3] : cA[3], src);
            uint32_t q0 = __shfl_sync(0xffffffffu, pt ? pkB0 : pkA0, src);
            uint32_t q1 = __shfl_sync(0xffffffffu, pt ? pkB1 : pkA1, src);

            uint32_t i00 = q0 & 0xffffu, i01 = q0 >> 16;
            uint32_t i10 = q1 & 0xffffu, i11 = q1 >> 16;

            float4 v00 = __ldg((const float4*)(pbase + (size_t)i00 * Ee));
            float4 v01 = __ldg((const float4*)(pbase + (size_t)i01 * Ee));
            float4 v10 = __ldg((const float4*)(pbase + (size_t)i10 * Ee));
            float4 v11 = __ldg((const float4*)(pbase + (size_t)i11 * Ee));

            acc.x = fmaf(c0, v00.x, fmaf(c1, v01.x, fmaf(c2, v10.x, fmaf(c3, v11.x, acc.x))));
            acc.y = fmaf(c0, v00.y, fmaf(c1, v01.y, fmaf(c2, v10.y, fmaf(c3, v11.y, acc.y))));
            acc.z = fmaf(c0, v00.z, fmaf(c1, v01.z, fmaf(c2, v10.z, fmaf(c3, v11.z, acc.z))));
            acc.w = fmaf(c0, v00.w, fmaf(c1, v01.w, fmaf(c2, v10.w, fmaf(c3, v11.w, acc.w))));
        }
    }

    *(float4*)(g_tmp + (size_t)bq * Ee + hh * HEAD_DIM + r * 4) = acc;
}

// ---------------------------------------------------------------------------
extern "C" void kernel_launch(void* const* d_in, const int* in_sizes, int n_in,
                              void* d_out, int out_size)
{
    const float* query = (const float*)d_in[0];
    const float* ref   = (const float*)d_in[1];
    const float* value = (const float*)d_in[2];
    const float* Wv    = (const float*)d_in[4];
    const float* bv    = (const float*)d_in[5];
    const float* Woff  = (const float*)d_in[6];
    const float* boff  = (const float*)d_in[7];
    const float* Wattn = (const float*)d_in[8];
    const float* battn = (const float*)d_in[9];
    const float* Wo    = (const float*)d_in[10];
    const float* bo    = (const float*)d_in[11];
    float* out = (float*)d_out;

    float *pv, *poffaw, *ptmp, *pbc;
    __nv_bfloat16 *pwhi, *pwlo;
    cudaGetSymbolAddress((void**)&pv,     g_v);
    cudaGetSymbolAddress((void**)&poffaw, g_offaw);
    cudaGetSymbolAddress((void**)&ptmp,   g_tmp);
    cudaGetSymbolAddress((void**)&pbc,    g_bias_comb);
    cudaGetSymbolAddress((void**)&pwhi,   g_wt_hi);
    cudaGetSymbolAddress((void**)&pwlo,   g_wt_lo);

    cudaFuncSetAttribute(gemm_f32_bf16x3,
                         cudaFuncAttributeMaxDynamicSharedMemorySize, 131072);

    // ---- prep (single launch) ----
    prep_weights_kernel<<<(WT_TOTAL + 255) / 256, 256>>>(Wv, Woff, Wattn, Wo, boff, battn);

    // ---- GEMM 1: g_v = value @ Wv + bv ----
    {
        dim3 grid(2, (MV + 127) / 128);
        gemm_f32_bf16x3<<<grid, 512, 131072>>>(value, pwhi + WT_WV, pwlo + WT_WV,
                                               bv, pv, MV, 256);
    }
    // ---- GEMM 2 (fused): g_offaw = query @ [Woff | Wattn] + [boff | battn] ----
    {
        dim3 grid(3, (MQ + 127) / 128);
        gemm_f32_bf16x3<<<grid, 512, 131072>>>(query, pwhi + WT_COMB, pwlo + WT_COMB,
                                               pbc, poffaw, MQ, 384);
    }
    // ---- sampler ----
    {
        int total_warps = Bb * LQ * 2;
        int blocks = (total_warps + 7) / 8;
        msda_sample_kernel<<<blocks, 256>>>(ref);
    }
    // ---- GEMM 3: out = g_tmp @ Wo + bo ----
    {
        dim3 grid(2, (MQ + 127) / 128);
        gemm_f32_bf16x3<<<grid, 512, 131072>>>(ptmp, pwhi + WT_WO, pwlo + WT_WO,
                                               bo, out, MQ, 256);
    }
}

// round 8
// speedup vs baseline: 3.6942x; 1.0669x over previous
#include <cuda_runtime.h>
#include <cuda_bf16.h>
#include <math.h>
#include <stdint.h>

#define Bb 4
#define LQ 8400
#define Ee 256
#define HEADS 8
#define LEVELS 4
#define POINTS 4
#define HEAD_DIM 32
#define LVTOT 8500
#define KDIM 256

#define MQ (Bb * LQ)     // 33600
#define MV (Bb * LVTOT)  // 34000

// ---------------- scratch (device globals; no allocation allowed) ----------
__device__ float g_v[MV * Ee];            // value @ Wv + bv (f32, sampler input)
__device__ float g_offaw[MQ * 384];       // [off(256) | aw(128)] fused GEMM output
__device__ float g_tmp[MQ * Ee];          // sampler output (f32)
__device__ float g_bias_comb[384];

// transposed weights [N][K] bf16 hi/lo
#define WT_WV    0
#define WT_COMB  65536
#define WT_WO    163840
#define WT_TOTAL 229376
__device__ __nv_bfloat16 g_wt_hi[WT_TOTAL];
__device__ __nv_bfloat16 g_wt_lo[WT_TOTAL];

// ---------------- helpers ----------------------------------------------
#define SMEM_SWIZZLE_128B(byte_offset) \
    ((byte_offset) ^ (((byte_offset) >> 3) & 0x70))

__device__ __forceinline__ uint32_t smem_u32(const void* p) {
    uint32_t a;
    asm("{ .reg .u64 t; cvta.to.shared.u64 t, %1; cvt.u32.u64 %0, t; }"
        : "=r"(a) : "l"(p));
    return a;
}

__device__ __forceinline__ void cp16(uint32_t dst, const void* src) {
    asm volatile("cp.async.cg.shared.global [%0], [%1], 16;"
                 :: "r"(dst), "l"(src));
}

__device__ __forceinline__ void cp_commit() {
    asm volatile("cp.async.commit_group;" ::: "memory");
}
__device__ __forceinline__ void cp_wait0() {
    asm volatile("cp.async.wait_group 0;" ::: "memory");
}

__device__ __forceinline__ void ldm_x4(uint32_t* r, uint32_t addr) {
    asm volatile("ldmatrix.sync.aligned.m8n8.x4.shared.b16 {%0,%1,%2,%3}, [%4];"
                 : "=r"(r[0]), "=r"(r[1]), "=r"(r[2]), "=r"(r[3]) : "r"(addr));
}

__device__ __forceinline__ void mma16816(float* c, const uint32_t* a, const uint32_t* b) {
    asm volatile("mma.sync.aligned.m16n8k16.row.col.f32.bf16.bf16.f32 "
                 "{%0,%1,%2,%3}, {%4,%5,%6,%7}, {%8,%9}, {%0,%1,%2,%3};"
                 : "+f"(c[0]), "+f"(c[1]), "+f"(c[2]), "+f"(c[3])
                 : "r"(a[0]), "r"(a[1]), "r"(a[2]), "r"(a[3]),
                   "r"(b[0]), "r"(b[1]));
}

__device__ __forceinline__ void split4(float4 v, uint2& ho, uint2& lo) {
    __nv_bfloat16 h0 = __float2bfloat16_rn(v.x);
    __nv_bfloat16 h1 = __float2bfloat16_rn(v.y);
    __nv_bfloat16 h2 = __float2bfloat16_rn(v.z);
    __nv_bfloat16 h3 = __float2bfloat16_rn(v.w);
    __nv_bfloat16 l0 = __float2bfloat16_rn(v.x - __bfloat162float(h0));
    __nv_bfloat16 l1 = __float2bfloat16_rn(v.y - __bfloat162float(h1));
    __nv_bfloat16 l2 = __float2bfloat16_rn(v.z - __bfloat162float(h2));
    __nv_bfloat16 l3 = __float2bfloat16_rn(v.w - __bfloat162float(h3));
    __nv_bfloat162 hp0; hp0.x = h0; hp0.y = h1;
    __nv_bfloat162 hp1; hp1.x = h2; hp1.y = h3;
    __nv_bfloat162 lp0; lp0.x = l0; lp0.y = l1;
    __nv_bfloat162 lp1; lp1.x = l2; lp1.y = l3;
    ho.x = *(uint32_t*)&hp0; ho.y = *(uint32_t*)&hp1;
    lo.x = *(uint32_t*)&lp0; lo.y = *(uint32_t*)&lp1;
}

// ---------------------------------------------------------------------------
// ONE prep kernel: all 4 weight transposes+splits + bias concat.
// ---------------------------------------------------------------------------
__global__ void prep_weights_kernel(const float* __restrict__ Wv,
                                    const float* __restrict__ Woff,
                                    const float* __restrict__ Wattn,
                                    const float* __restrict__ Wo,
                                    const float* __restrict__ boff,
                                    const float* __restrict__ battn)
{
    int idx = blockIdx.x * blockDim.x + threadIdx.x;
    if (idx < 384)
        g_bias_comb[idx] = (idx < 256) ? boff[idx] : battn[idx - 256];
    if (idx >= WT_TOTAL) return;

    const float* W;
    int Nd, out, t = idx;
    if (t < 65536)        { W = Wv;    Nd = 256; out = WT_WV; }
    else if (t < 131072)  { W = Woff;  Nd = 256; out = WT_COMB;          t -= 65536; }
    else if (t < 163840)  { W = Wattn; Nd = 128; out = WT_COMB + 65536;  t -= 131072; }
    else                  { W = Wo;    Nd = 256; out = WT_WO;            t -= 163840; }

    int k = t / Nd, n = t % Nd;
    float v = W[k * Nd + n];
    __nv_bfloat16 h = __float2bfloat16_rn(v);
    g_wt_hi[out + n * 256 + k] = h;
    g_wt_lo[out + n * 256 + k] = __float2bfloat16_rn(v - __bfloat162float(h));
}

// ---------------------------------------------------------------------------
// mma.sync bf16x3 GEMM. CTA tile 64x128, 256 threads (8 warps, warp 32x32).
// Single-stage smem 48KB -> 3 CTAs/SM; inter-CTA overlap hides loads.
// Dual-problem dispatch: blocks [0, nblk1) -> problem 1, rest -> problem 2.
// ---------------------------------------------------------------------------
__global__ __launch_bounds__(256, 3)
void gemm_dual_bf16x3(const float* __restrict__ A1,
                      const __nv_bfloat16* __restrict__ Bhi1,
                      const __nv_bfloat16* __restrict__ Blo1,
                      const float* __restrict__ bias1,
                      float* __restrict__ C1, int M1, int N1, int nc1, int nblk1,
                      const float* __restrict__ A2,
                      const __nv_bfloat16* __restrict__ Bhi2,
                      const __nv_bfloat16* __restrict__ Blo2,
                      const float* __restrict__ bias2,
                      float* __restrict__ C2, int M2, int N2, int nc2)
{
    extern __shared__ char smem[];
    // layout: A_hi 0..8K | A_lo 8K..16K | B_hi 16K..32K | B_lo 32K..48K
    const uint32_t sa_hi = smem_u32(smem);
    const uint32_t sa_lo = sa_hi + 8192u;
    const uint32_t sb_hi = sa_hi + 16384u;
    const uint32_t sb_lo = sa_hi + 32768u;

    const float* A; const __nv_bfloat16* Bhi; const __nv_bfloat16* Blo;
    const float* bias; float* C;
    int M, N, brow, bcol;
    {
        int bid = blockIdx.x;
        if (bid < nblk1) {
            A = A1; Bhi = Bhi1; Blo = Blo1; bias = bias1; C = C1; M = M1; N = N1;
            brow = (bid / nc1) * 64; bcol = (bid % nc1) * 128;
        } else {
            bid -= nblk1;
            A = A2; Bhi = Bhi2; Blo = Blo2; bias = bias2; C = C2; M = M2; N = N2;
            brow = (bid / nc2) * 64; bcol = (bid % nc2) * 128;
        }
    }

    const int tid = threadIdx.x, lane = tid & 31, wid = tid >> 5;
    const int wr = (wid >> 2) * 32;   // 0 or 32
    const int wc = (wid & 3) * 32;    // 0,32,64,96

    float acc[2][4][4];
#pragma unroll
    for (int i = 0; i < 2; i++)
#pragma unroll
        for (int j = 0; j < 4; j++)
#pragma unroll
            for (int k = 0; k < 4; k++) acc[i][j][k] = 0.f;

    const int a_r  = wr + (lane & 15);
    const int a_kx = (lane >> 4) << 4;
    const int b_r0 = wc + (lane & 7) + ((lane >> 4) << 3);
    const int b_kx = ((lane >> 3) & 1) << 4;

    const int nk = KDIM / 64;   // 4
    for (int kc = 0; kc < nk; kc++) {
        if (kc) __syncthreads();   // previous compute must finish before overwrite

        // ---- B chunk via cp.async (128 rows x 128B, hi+lo) ----
#pragma unroll
        for (int i = 0; i < 4; i++) {
            int t = i * 256 + tid;
            int r = t >> 3, j = t & 7;
            uint32_t d = SMEM_SWIZZLE_128B((uint32_t)(r * 128 + j * 16));
            size_t src = (size_t)(bcol + r) * KDIM + kc * 64 + j * 8;
            cp16(sb_hi + d, Bhi + src);
            cp16(sb_lo + d, Blo + src);
        }
        cp_commit();

        // ---- A chunk via LDG -> split -> STS (64 rows x 64 f32) ----
        float4 a4[4];
#pragma unroll
        for (int i = 0; i < 4; i++) {
            int t = i * 256 + tid;
            int r = t >> 4, jc = t & 15;
            a4[i] = (brow + r < M)
                ? __ldg((const float4*)(A + (size_t)(brow + r) * KDIM + kc * 64 + jc * 4))
                : make_float4(0.f, 0.f, 0.f, 0.f);
        }
#pragma unroll
        for (int i = 0; i < 4; i++) {
            int t = i * 256 + tid;
            int r = t >> 4, jc = t & 15;
            uint32_t d = SMEM_SWIZZLE_128B((uint32_t)(r * 128 + (jc >> 1) * 16)) + (jc & 1) * 8;
            uint2 ho, lo;
            split4(a4[i], ho, lo);
            *(uint2*)(smem + (sa_hi - smem_u32(smem)) + d) = ho;   // = smem + d
            *(uint2*)(smem + 8192u + d) = lo;
        }
        cp_wait0();
        __syncthreads();

        // ---- compute ----
#pragma unroll
        for (int kk = 0; kk < 4; kk++) {
            const uint32_t kbA = (uint32_t)(kk * 32 + a_kx);
            const uint32_t kbB = (uint32_t)(kk * 32 + b_kx);

            uint32_t ahi[2][4], bhi[4][2];
#pragma unroll
            for (int mi = 0; mi < 2; mi++)
                ldm_x4(ahi[mi], sa_hi + SMEM_SWIZZLE_128B((uint32_t)((a_r + mi * 16) * 128) + kbA));
#pragma unroll
            for (int nj = 0; nj < 2; nj++) {
                uint32_t rr[4];
                ldm_x4(rr, sb_hi + SMEM_SWIZZLE_128B((uint32_t)((b_r0 + nj * 16) * 128) + kbB));
                bhi[nj * 2][0] = rr[0]; bhi[nj * 2][1] = rr[1];
                bhi[nj * 2 + 1][0] = rr[2]; bhi[nj * 2 + 1][1] = rr[3];
            }
#pragma unroll
            for (int mi = 0; mi < 2; mi++)
#pragma unroll
                for (int ni = 0; ni < 4; ni++)
                    mma16816(acc[mi][ni], ahi[mi], bhi[ni]);

            uint32_t blo[4][2];
#pragma unroll
            for (int nj = 0; nj < 2; nj++) {
                uint32_t rr[4];
                ldm_x4(rr, sb_lo + SMEM_SWIZZLE_128B((uint32_t)((b_r0 + nj * 16) * 128) + kbB));
                blo[nj * 2][0] = rr[0]; blo[nj * 2][1] = rr[1];
                blo[nj * 2 + 1][0] = rr[2]; blo[nj * 2 + 1][1] = rr[3];
            }
#pragma unroll
            for (int mi = 0; mi < 2; mi++)
#pragma unroll
                for (int ni = 0; ni < 4; ni++)
                    mma16816(acc[mi][ni], ahi[mi], blo[ni]);

            uint32_t alo[2][4];
#pragma unroll
            for (int mi = 0; mi < 2; mi++)
                ldm_x4(alo[mi], sa_lo + SMEM_SWIZZLE_128B((uint32_t)((a_r + mi * 16) * 128) + kbA));
#pragma unroll
            for (int mi = 0; mi < 2; mi++)
#pragma unroll
                for (int ni = 0; ni < 4; ni++)
                    mma16816(acc[mi][ni], alo[mi], bhi[ni]);
        }
    }

    // ---- epilogue: bias + float2 stores ----
    const int row0 = brow + wr + (lane >> 2);
#pragma unroll
    for (int ni = 0; ni < 4; ni++) {
        int col = bcol + wc + ni * 8 + (lane & 3) * 2;
        float2 bb = *(const float2*)&bias[col];
#pragma unroll
        for (int mi = 0; mi < 2; mi++) {
            int r0 = row0 + mi * 16;
            if (r0 < M) {
                float2 o;
                o.x = acc[mi][ni][0] + bb.x;
                o.y = acc[mi][ni][1] + bb.y;
                *(float2*)(C + (size_t)r0 * N + col) = o;
            }
            int r1 = r0 + 8;
            if (r1 < M) {
                float2 o;
                o.x = acc[mi][ni][2] + bb.x;
                o.y = acc[mi][ni][3] + bb.y;
                *(float2*)(C + (size_t)r1 * N + col) = o;
            }
        }
    }
}

// ---------------------------------------------------------------------------
// Fused softmax + bilinear sampling (owner-lane precompute, unchanged).
// ---------------------------------------------------------------------------
__global__ __launch_bounds__(256)
void msda_sample_kernel(const float* __restrict__ ref)
{
    int warp_global = blockIdx.x * (blockDim.x >> 5) + (threadIdx.x >> 5);
    if (warp_global >= Bb * LQ * 2) return;
    int lane = threadIdx.x & 31;
    int g = lane >> 3;
    int r = lane & 7;

    int hpair = warp_global & 1;
    int bq    = warp_global >> 1;
    int b     = bq / LQ;
    int hh    = hpair * 4 + g;

    const float2* awp = (const float2*)(g_offaw + (size_t)bq * 384 + 256 + hh * 16);
    float2 lg = awp[r];
    float m = fmaxf(lg.x, lg.y);
#pragma unroll
    for (int o = 4; o > 0; o >>= 1) m = fmaxf(m, __shfl_xor_sync(0xffffffffu, m, o));
    float e0 = __expf(lg.x - m);
    float e1 = __expf(lg.y - m);
    float s = e0 + e1;
#pragma unroll
    for (int o = 4; o > 0; o >>= 1) s += __shfl_xor_sync(0xffffffffu, s, o);
    float inv = 1.f / s;
    float w0 = e0 * inv;
    float w1 = e1 * inv;

    const float4* offp = (const float4*)(g_offaw + (size_t)bq * 384 + hh * 32);
    float4 off4 = offp[r];

    int l  = r >> 1;
    int HW = 80 >> l;
    int start = (l > 0 ? 6400 : 0) + (l > 1 ? 1600 : 0) + (l > 2 ? 400 : 0);
    float fHW = (float)HW;
    float2 rxy = __ldg((const float2*)ref + (size_t)bq * 4 + l);

    float cA[4], cB[4];
    uint32_t pkA0, pkA1, pkB0, pkB1;
#pragma unroll
    for (int pt = 0; pt < 2; pt++) {
        float ox = pt ? off4.z : off4.x;
        float oy = pt ? off4.w : off4.y;
        float aw = pt ? w1 : w0;

        float x = fmaf(rxy.x, fHW, ox - 0.5f);
        float y = fmaf(rxy.y, fHW, oy - 0.5f);
        float x0f = floorf(x), y0f = floorf(y);
        float wx = x - x0f, wy = y - y0f;
        int x0 = (int)x0f, y0 = (int)y0f;
        int x1 = x0 + 1,   y1 = y0 + 1;

        float vx0 = (x0 >= 0 && x0 < HW) ? 1.f : 0.f;
        float vx1 = (x1 >= 0 && x1 < HW) ? 1.f : 0.f;
        float vy0 = (y0 >= 0 && y0 < HW) ? 1.f : 0.f;
        float vy1 = (y1 >= 0 && y1 < HW) ? 1.f : 0.f;

        int cx0 = min(max(x0, 0), HW - 1);
        int cx1 = min(max(x1, 0), HW - 1);
        int cy0 = min(max(y0, 0), HW - 1);
        int cy1 = min(max(y1, 0), HW - 1);

        uint32_t p00 = (uint32_t)(start + cy0 * HW + cx0);
        uint32_t p01 = (uint32_t)(start + cy0 * HW + cx1);
        uint32_t p10 = (uint32_t)(start + cy1 * HW + cx0);
        uint32_t p11 = (uint32_t)(start + cy1 * HW + cx1);

        float wx1 = 1.f - wx, wy1 = 1.f - wy;
        float c0 = aw * wx1 * wy1 * vx0 * vy0;
        float c1 = aw * wx  * wy1 * vx1 * vy0;
        float c2 = aw * wx1 * wy  * vx0 * vy1;
        float c3 = aw * wx  * wy  * vx1 * vy1;

        if (pt == 0) {
            cA[0] = c0; cA[1] = c1; cA[2] = c2; cA[3] = c3;
            pkA0 = p00 | (p01 << 16); pkA1 = p10 | (p11 << 16);
        } else {
            cB[0] = c0; cB[1] = c1; cB[2] = c2; cB[3] = c3;
            pkB0 = p00 | (p01 << 16); pkB1 = p10 | (p11 << 16);
        }
    }

    const float* pbase = g_v + (size_t)b * LVTOT * Ee + hh * HEAD_DIM + r * 4;
    float4 acc = make_float4(0.f, 0.f, 0.f, 0.f);

#pragma unroll
    for (int j = 0; j < 8; j++) {
        int src = (g << 3) + j;
#pragma unroll
        for (int pt = 0; pt < 2; pt++) {
            float c0 = __shfl_sync(0xffffffffu, pt ? cB[0] : cA[0], src);
            float c1 = __shfl_sync(0xffffffffu, pt ? cB[1] : cA[1], src);
            float c2 = __shfl_sync(0xffffffffu, pt ? cB[2] : cA[2], src);
            float c3 = __shfl_sync(0xffffffffu, pt ? cB[3] : cA[3], src);
            uint32_t q0 = __shfl_sync(0xffffffffu, pt ? pkB0 : pkA0, src);
            uint32_t q1 = __shfl_sync(0xffffffffu, pt ? pkB1 : pkA1, src);

            uint32_t i00 = q0 & 0xffffu, i01 = q0 >> 16;
            uint32_t i10 = q1 & 0xffffu, i11 = q1 >> 16;

            float4 v00 = __ldg((const float4*)(pbase + (size_t)i00 * Ee));
            float4 v01 = __ldg((const float4*)(pbase + (size_t)i01 * Ee));
            float4 v10 = __ldg((const float4*)(pbase + (size_t)i10 * Ee));
            float4 v11 = __ldg((const float4*)(pbase + (size_t)i11 * Ee));

            acc.x = fmaf(c0, v00.x, fmaf(c1, v01.x, fmaf(c2, v10.x, fmaf(c3, v11.x, acc.x))));
            acc.y = fmaf(c0, v00.y, fmaf(c1, v01.y, fmaf(c2, v10.y, fmaf(c3, v11.y, acc.y))));
            acc.z = fmaf(c0, v00.z, fmaf(c1, v01.z, fmaf(c2, v10.z, fmaf(c3, v11.z, acc.z))));
            acc.w = fmaf(c0, v00.w, fmaf(c1, v01.w, fmaf(c2, v10.w, fmaf(c3, v11.w, acc.w))));
        }
    }

    *(float4*)(g_tmp + (size_t)bq * Ee + hh * HEAD_DIM + r * 4) = acc;
}

// ---------------------------------------------------------------------------
extern "C" void kernel_launch(void* const* d_in, const int* in_sizes, int n_in,
                              void* d_out, int out_size)
{
    const float* query = (const float*)d_in[0];
    const float* ref   = (const float*)d_in[1];
    const float* value = (const float*)d_in[2];
    const float* Wv    = (const float*)d_in[4];
    const float* bv    = (const float*)d_in[5];
    const float* Woff  = (const float*)d_in[6];
    const float* boff  = (const float*)d_in[7];
    const float* Wattn = (const float*)d_in[8];
    const float* battn = (const float*)d_in[9];
    const float* Wo    = (const float*)d_in[10];
    const float* bo    = (const float*)d_in[11];
    float* out = (float*)d_out;

    float *pv, *poffaw, *ptmp, *pbc;
    __nv_bfloat16 *pwhi, *pwlo;
    cudaGetSymbolAddress((void**)&pv,     g_v);
    cudaGetSymbolAddress((void**)&poffaw, g_offaw);
    cudaGetSymbolAddress((void**)&ptmp,   g_tmp);
    cudaGetSymbolAddress((void**)&pbc,    g_bias_comb);
    cudaGetSymbolAddress((void**)&pwhi,   g_wt_hi);
    cudaGetSymbolAddress((void**)&pwlo,   g_wt_lo);

    cudaFuncSetAttribute(gemm_dual_bf16x3,
                         cudaFuncAttributeMaxDynamicSharedMemorySize, 49152);

    // ---- prep (single launch) ----
    prep_weights_kernel<<<(WT_TOTAL + 255) / 256, 256>>>(Wv, Woff, Wattn, Wo, boff, battn);

    // ---- GEMM 1+2 merged: g_v = value@Wv+bv  AND  g_offaw = query@[Woff|Wattn]+bias ----
    {
        const int rows1 = (MV + 63) / 64;          // 532
        const int nblk1 = rows1 * 2;               // 1064  (N=256 -> nc1=2)
        const int rows2 = (MQ + 63) / 64;          // 525
        const int nblk2 = rows2 * 3;               // 1575  (N=384 -> nc2=3)
        gemm_dual_bf16x3<<<nblk1 + nblk2, 256, 49152>>>(
            value, pwhi + WT_WV,   pwlo + WT_WV,   bv,  pv,     MV, 256, 2, nblk1,
            query, pwhi + WT_COMB, pwlo + WT_COMB, pbc, poffaw, MQ, 384, 3);
    }
    // ---- sampler ----
    {
        int total_warps = Bb * LQ * 2;
        int blocks = (total_warps + 7) / 8;
        msda_sample_kernel<<<blocks, 256>>>(ref);
    }
    // ---- GEMM 3: out = g_tmp @ Wo + bo ----
    {
        const int rows3 = (MQ + 63) / 64;          // 525
        const int nblk3 = rows3 * 2;               // 1050
        gemm_dual_bf16x3<<<nblk3, 256, 49152>>>(
            ptmp, pwhi + WT_WO, pwlo + WT_WO, bo, out, MQ, 256, 2, nblk3,
            ptmp, pwhi + WT_WO, pwlo + WT_WO, bo, out, MQ, 256, 2);
    }
}